// round 9
// baseline (speedup 1.0000x reference)
#include <cuda_runtime.h>
#include <cuda_bf16.h>
#include <cstddef>

// ============================================================================
// Problem constants: B=4, S=1024, D=1024, H=16, DK=64, DFF=4096
// ============================================================================
#define BB   4
#define SS   1024
#define DD   1024
#define HH   16
#define DKK  64
#define DFF_ 4096
#define ROWS (BB * SS)   // 4096

// ---------------------------------------------------------------------------
// Scratch (no cudaMalloc allowed): __device__ globals
// ---------------------------------------------------------------------------
__device__ float g_xn [ROWS * DD];          // 16 MB (reused for xn1 and xn2)
__device__ float g_q  [ROWS * DD];          // [B,H,S,DK]
__device__ float g_k  [ROWS * DD];
__device__ float g_v  [ROWS * DD];
__device__ float g_ctx[ROWS * DD];          // [B,S,D]
__device__ float g_x1 [ROWS * DD];          // residual-1 output
__device__ float g_ff [ (size_t)ROWS * DFF_ ]; // 64 MB hidden

// ---------------------------------------------------------------------------
// f32x2 packed-FMA helpers (sm_100+; ptxas never emits these from C++)
// ---------------------------------------------------------------------------
__device__ __forceinline__ unsigned long long pack2(float lo, float hi) {
    unsigned long long r;
    asm("mov.b64 %0, {%1, %2};" : "=l"(r) : "f"(lo), "f"(hi));
    return r;
}
__device__ __forceinline__ void unpack2(unsigned long long v, float& lo, float& hi) {
    asm("mov.b64 {%0, %1}, %2;" : "=f"(lo), "=f"(hi) : "l"(v));
}
__device__ __forceinline__ unsigned long long ffma2(unsigned long long a,
                                                    unsigned long long b,
                                                    unsigned long long c) {
    unsigned long long d;
    asm("fma.rn.f32x2 %0, %1, %2, %3;" : "=l"(d) : "l"(a), "l"(b), "l"(c));
    return d;
}

// ============================================================================
// LayerNorm: y = alpha*(x-mean)/(std+eps)+beta, std with ddof=1, eps on std.
// One block per row (1024 cols), 256 threads, float4 per thread.
// ============================================================================
__global__ void __launch_bounds__(256)
layernorm_kernel(const float* __restrict__ x, float* __restrict__ out,
                 const float* __restrict__ alpha, const float* __restrict__ beta)
{
    __shared__ float red[16];
    const int row = blockIdx.x;
    const int tid = threadIdx.x;
    const float* xr = x + (size_t)row * DD;

    float4 v = *(const float4*)(xr + tid * 4);
    float s = v.x + v.y + v.z + v.w;
    #pragma unroll
    for (int o = 16; o > 0; o >>= 1) s += __shfl_xor_sync(0xffffffffu, s, o);
    if ((tid & 31) == 0) red[tid >> 5] = s;
    __syncthreads();
    float tot = red[0] + red[1] + red[2] + red[3] + red[4] + red[5] + red[6] + red[7];
    float mean = tot * (1.0f / (float)DD);

    float dx0 = v.x - mean, dx1 = v.y - mean, dx2 = v.z - mean, dx3 = v.w - mean;
    float q = dx0 * dx0 + dx1 * dx1 + dx2 * dx2 + dx3 * dx3;
    #pragma unroll
    for (int o = 16; o > 0; o >>= 1) q += __shfl_xor_sync(0xffffffffu, q, o);
    if ((tid & 31) == 0) red[8 + (tid >> 5)] = q;
    __syncthreads();
    float ssq = red[8] + red[9] + red[10] + red[11] + red[12] + red[13] + red[14] + red[15];

    float stdv = sqrtf(ssq * (1.0f / (float)(DD - 1)));   // ddof=1
    float a = __ldg(alpha), b = __ldg(beta);
    float r = a / (stdv + 1e-6f);                          // eps added to STD

    float4 o4 = make_float4(dx0 * r + b, dx1 * r + b, dx2 * r + b, dx3 * r + b);
    *(float4*)(out + (size_t)row * DD + tid * 4) = o4;
}

// ============================================================================
// SGEMM  C[M,N] = A[M,K] @ W[K,N] + bias, f32x2 packed FMA.
// 128x128 block tile, BK=16, 256 threads, 8x8 per thread (N-pairs).
// A tile stored in SMEM pre-duplicated as (a,a) u64 pairs -> zero pack cost
// in the inner loop.  MODE: 1 = scatter to [B,H,S,DK], 2 = +res, 3 = ReLU.
// ============================================================================
#define GBM 128
#define GBN 128
#define GBK 16

template<int MODE>
__global__ void __launch_bounds__(256, 2)
sgemm_f32x2(const float* __restrict__ A, const float* __restrict__ W,
            const float* __restrict__ bias, const float* __restrict__ res,
            float* __restrict__ out, int M, int N, int K)
{
    __shared__ __align__(16) unsigned long long As2[GBK][GBM];
    __shared__ __align__(16) float Bs[GBK][GBN];

    const int tid = threadIdx.x;
    const int ty  = tid >> 4;          // 0..15 -> rows ty*8..ty*8+7
    const int tx  = tid & 15;          // 0..15 -> cols tx*8..tx*8+7
    const int m0  = blockIdx.y * GBM;
    const int n0  = blockIdx.x * GBN;

    unsigned long long acc[8][4];
    #pragma unroll
    for (int i = 0; i < 8; i++)
        #pragma unroll
        for (int j = 0; j < 4; j++) acc[i][j] = 0ull;

    float4 pa[2], pb[2];

    // ---- load tile 0 into registers ----
    #pragma unroll
    for (int r = 0; r < 2; r++) {
        int idx = tid + r * 256;
        pa[r] = *(const float4*)(A + (size_t)(m0 + (idx >> 2)) * K + (idx & 3) * 4);
        pb[r] = *(const float4*)(W + (size_t)(idx >> 5) * N + n0 + (idx & 31) * 4);
    }
    // ---- store tile 0 to SMEM ----
    #pragma unroll
    for (int r = 0; r < 2; r++) {
        int idx = tid + r * 256;
        int arow = idx >> 2, ac4 = idx & 3;
        As2[ac4 * 4 + 0][arow] = pack2(pa[r].x, pa[r].x);
        As2[ac4 * 4 + 1][arow] = pack2(pa[r].y, pa[r].y);
        As2[ac4 * 4 + 2][arow] = pack2(pa[r].z, pa[r].z);
        As2[ac4 * 4 + 3][arow] = pack2(pa[r].w, pa[r].w);
        int brow = idx >> 5, bc4 = idx & 31;
        *(float4*)&Bs[brow][bc4 * 4] = pb[r];
    }
    __syncthreads();

    const int ktiles = K / GBK;
    for (int t = 0; t < ktiles; t++) {
        const bool has_next = (t + 1 < ktiles);
        if (has_next) {
            const int kt = (t + 1) * GBK;
            #pragma unroll
            for (int r = 0; r < 2; r++) {
                int idx = tid + r * 256;
                pa[r] = *(const float4*)(A + (size_t)(m0 + (idx >> 2)) * K + kt + (idx & 3) * 4);
                pb[r] = *(const float4*)(W + (size_t)(kt + (idx >> 5)) * N + n0 + (idx & 31) * 4);
            }
        }
        // ---- compute ----
        #pragma unroll
        for (int kk = 0; kk < GBK; kk++) {
            const ulonglong2* ap = (const ulonglong2*)&As2[kk][ty * 8];
            ulonglong2 a01 = ap[0], a23 = ap[1], a45 = ap[2], a67 = ap[3];
            const ulonglong2* bp = (const ulonglong2*)&Bs[kk][tx * 8];
            ulonglong2 b01 = bp[0], b23 = bp[1];
            unsigned long long a[8] = {a01.x, a01.y, a23.x, a23.y, a45.x, a45.y, a67.x, a67.y};
            unsigned long long b[4] = {b01.x, b01.y, b23.x, b23.y};
            #pragma unroll
            for (int i = 0; i < 8; i++) {
                acc[i][0] = ffma2(a[i], b[0], acc[i][0]);
                acc[i][1] = ffma2(a[i], b[1], acc[i][1]);
                acc[i][2] = ffma2(a[i], b[2], acc[i][2]);
                acc[i][3] = ffma2(a[i], b[3], acc[i][3]);
            }
        }
        if (has_next) {
            __syncthreads();
            #pragma unroll
            for (int r = 0; r < 2; r++) {
                int idx = tid + r * 256;
                int arow = idx >> 2, ac4 = idx & 3;
                As2[ac4 * 4 + 0][arow] = pack2(pa[r].x, pa[r].x);
                As2[ac4 * 4 + 1][arow] = pack2(pa[r].y, pa[r].y);
                As2[ac4 * 4 + 2][arow] = pack2(pa[r].z, pa[r].z);
                As2[ac4 * 4 + 3][arow] = pack2(pa[r].w, pa[r].w);
                int brow = idx >> 5, bc4 = idx & 31;
                *(float4*)&Bs[brow][bc4 * 4] = pb[r];
            }
            __syncthreads();
        }
    }

    // ---- epilogue ----
    float bl[8];
    *(float4*)&bl[0] = *(const float4*)(bias + n0 + tx * 8);
    *(float4*)&bl[4] = *(const float4*)(bias + n0 + tx * 8 + 4);

    #pragma unroll
    for (int i = 0; i < 8; i++) {
        const int m = m0 + ty * 8 + i;
        #pragma unroll
        for (int j = 0; j < 4; j++) {
            float v0, v1;
            unpack2(acc[i][j], v0, v1);
            const int n = n0 + tx * 8 + 2 * j;
            v0 += bl[2 * j];
            v1 += bl[2 * j + 1];
            if (MODE == 3) { v0 = fmaxf(v0, 0.0f); v1 = fmaxf(v1, 0.0f); }
            if (MODE == 2) {
                float2 rv = *(const float2*)(res + (size_t)m * N + n);
                v0 += rv.x; v1 += rv.y;
            }
            if (MODE == 1) {
                // scatter to [B,H,S,DK]: m = b*S+s, n = h*DK+dk
                int b_ = m >> 10, s = m & 1023;
                int h_ = n >> 6,  dk = n & 63;
                float* o = out + ((size_t)(b_ * HH + h_) * SS + s) * DKK + dk;
                o[0] = v0; o[1] = v1;   // dk even -> same head for dk, dk+1
            } else {
                *(float2*)(out + (size_t)m * N + n) = make_float2(v0, v1);
            }
        }
    }
}

// ============================================================================
// Flash attention, fp32. One block = one (b,h) x 64-query tile.
// 256 threads: ty(16) x tx(16), 4x4 output micro-tile per thread.
// Online softmax over 16 key tiles of 64.  SMEM (dynamic, 69.6 KB):
//   Qs[dk][q] (transposed, pre-scaled by 1/sqrt(DK)), Ks[dk][key] (transposed),
//   Vs[key][dk], Ps[q][key] — all row stride 68 (16B-aligned, conflict-free).
// ============================================================================
#define ATT_STRIDE 68
#define ATT_SMEM_BYTES (4 * 64 * ATT_STRIDE * (int)sizeof(float))

__global__ void __launch_bounds__(256)
attention_kernel(const float* __restrict__ q, const float* __restrict__ k,
                 const float* __restrict__ v, const int* __restrict__ mask,
                 float* __restrict__ ctx)
{
    extern __shared__ float sm[];
    float* Qs = sm;
    float* Ks = sm + 64 * ATT_STRIDE;
    float* Vs = sm + 2 * 64 * ATT_STRIDE;
    float* Ps = sm + 3 * 64 * ATT_STRIDE;

    const int tid = threadIdx.x;
    const int ty = tid >> 4, tx = tid & 15;
    const int bh = blockIdx.y;             // 0..63
    const int b  = bh >> 4, h = bh & 15;
    const int q0 = blockIdx.x * 64;

    const float* qb = q + (size_t)bh * (SS * DKK);
    const float* kb = k + (size_t)bh * (SS * DKK);
    const float* vb = v + (size_t)bh * (SS * DKK);

    // Load Q tile transposed + pre-scaled by 1/sqrt(DK) = 0.125
    #pragma unroll
    for (int r = 0; r < 4; r++) {
        int idx = tid + r * 256;
        int s = idx >> 4, c4 = idx & 15;
        float4 t = *(const float4*)(qb + (size_t)(q0 + s) * DKK + c4 * 4);
        Qs[(c4 * 4 + 0) * ATT_STRIDE + s] = t.x * 0.125f;
        Qs[(c4 * 4 + 1) * ATT_STRIDE + s] = t.y * 0.125f;
        Qs[(c4 * 4 + 2) * ATT_STRIDE + s] = t.z * 0.125f;
        Qs[(c4 * 4 + 3) * ATT_STRIDE + s] = t.w * 0.125f;
    }

    float m_run[4], l_run[4], acc[4][4];
    #pragma unroll
    for (int i = 0; i < 4; i++) {
        m_run[i] = -1e30f; l_run[i] = 0.0f;
        #pragma unroll
        for (int j = 0; j < 4; j++) acc[i][j] = 0.0f;
    }

    for (int kt = 0; kt < 16; kt++) {
        __syncthreads();   // previous PV reads of Ks/Vs/Ps complete (and Qs ready at kt=0)
        #pragma unroll
        for (int r = 0; r < 4; r++) {
            int idx = tid + r * 256;
            int s = idx >> 4, c4 = idx & 15;
            float4 tk = *(const float4*)(kb + (size_t)(kt * 64 + s) * DKK + c4 * 4);
            Ks[(c4 * 4 + 0) * ATT_STRIDE + s] = tk.x;
            Ks[(c4 * 4 + 1) * ATT_STRIDE + s] = tk.y;
            Ks[(c4 * 4 + 2) * ATT_STRIDE + s] = tk.z;
            Ks[(c4 * 4 + 3) * ATT_STRIDE + s] = tk.w;
            float4 tv = *(const float4*)(vb + (size_t)(kt * 64 + s) * DKK + c4 * 4);
            *(float4*)&Vs[s * ATT_STRIDE + c4 * 4] = tv;
        }
        __syncthreads();

        // ---- scores: sc[i][j] = sum_k Q[qrow][k]*K[key][k] (pre-scaled) ----
        float sc[4][4];
        #pragma unroll
        for (int i = 0; i < 4; i++)
            #pragma unroll
            for (int j = 0; j < 4; j++) sc[i][j] = 0.0f;

        #pragma unroll 16
        for (int kk = 0; kk < 64; kk++) {
            float4 qv = *(const float4*)&Qs[kk * ATT_STRIDE + ty * 4];
            float4 kv = *(const float4*)&Ks[kk * ATT_STRIDE + tx * 4];
            float qa[4] = {qv.x, qv.y, qv.z, qv.w};
            #pragma unroll
            for (int i = 0; i < 4; i++) {
                sc[i][0] += qa[i] * kv.x;
                sc[i][1] += qa[i] * kv.y;
                sc[i][2] += qa[i] * kv.z;
                sc[i][3] += qa[i] * kv.w;
            }
        }

        // ---- mask (src_mask shape [B,1,1,S]) ----
        const int key0 = kt * 64 + tx * 4;
        #pragma unroll
        for (int j = 0; j < 4; j++) {
            if (__ldg(mask + b * SS + key0 + j) == 0) {
                sc[0][j] = -1e9f; sc[1][j] = -1e9f; sc[2][j] = -1e9f; sc[3][j] = -1e9f;
            }
        }

        // ---- online softmax (row reductions over 16 lanes) ----
        #pragma unroll
        for (int i = 0; i < 4; i++) {
            float mt = fmaxf(fmaxf(sc[i][0], sc[i][1]), fmaxf(sc[i][2], sc[i][3]));
            mt = fmaxf(mt, __shfl_xor_sync(0xffffffffu, mt, 1, 16));
            mt = fmaxf(mt, __shfl_xor_sync(0xffffffffu, mt, 2, 16));
            mt = fmaxf(mt, __shfl_xor_sync(0xffffffffu, mt, 4, 16));
            mt = fmaxf(mt, __shfl_xor_sync(0xffffffffu, mt, 8, 16));
            float mn   = fmaxf(m_run[i], mt);
            float corr = __expf(m_run[i] - mn);
            m_run[i] = mn;
            float rs = 0.0f;
            #pragma unroll
            for (int j = 0; j < 4; j++) { sc[i][j] = __expf(sc[i][j] - mn); rs += sc[i][j]; }
            rs += __shfl_xor_sync(0xffffffffu, rs, 1, 16);
            rs += __shfl_xor_sync(0xffffffffu, rs, 2, 16);
            rs += __shfl_xor_sync(0xffffffffu, rs, 4, 16);
            rs += __shfl_xor_sync(0xffffffffu, rs, 8, 16);
            l_run[i] = l_run[i] * corr + rs;
            #pragma unroll
            for (int j = 0; j < 4; j++) acc[i][j] *= corr;
            *(float4*)&Ps[(ty * 4 + i) * ATT_STRIDE + tx * 4] =
                make_float4(sc[i][0], sc[i][1], sc[i][2], sc[i][3]);
        }
        __syncthreads();

        // ---- O += P @ V ----
        #pragma unroll 8
        for (int c = 0; c < 64; c++) {
            float4 vv = *(const float4*)&Vs[c * ATT_STRIDE + tx * 4];
            #pragma unroll
            for (int i = 0; i < 4; i++) {
                float p = Ps[(ty * 4 + i) * ATT_STRIDE + c];
                acc[i][0] += p * vv.x;
                acc[i][1] += p * vv.y;
                acc[i][2] += p * vv.z;
                acc[i][3] += p * vv.w;
            }
        }
    }

    // ---- normalize + write ctx[b, s, h*DK + dk] ----
    #pragma unroll
    for (int i = 0; i < 4; i++) {
        float rinv = __fdividef(1.0f, l_run[i]);
        int s = q0 + ty * 4 + i;
        float4 o = make_float4(acc[i][0] * rinv, acc[i][1] * rinv,
                               acc[i][2] * rinv, acc[i][3] * rinv);
        *(float4*)(ctx + ((size_t)(b * SS + s)) * DD + h * DKK + tx * 4) = o;
    }
}

// ============================================================================
// Launch
// ============================================================================
extern "C" void kernel_launch(void* const* d_in, const int* in_sizes, int n_in,
                              void* d_out, int out_size)
{
    const float* x      = (const float*)d_in[0];
    const int*   mask   = (const int*)  d_in[1];
    const float* wq     = (const float*)d_in[2];
    const float* bq     = (const float*)d_in[3];
    const float* wk     = (const float*)d_in[4];
    const float* bk     = (const float*)d_in[5];
    const float* wv     = (const float*)d_in[6];
    const float* bv     = (const float*)d_in[7];
    const float* wo     = (const float*)d_in[8];
    const float* bo     = (const float*)d_in[9];
    const float* w1     = (const float*)d_in[10];
    const float* b1     = (const float*)d_in[11];
    const float* w2     = (const float*)d_in[12];
    const float* b2     = (const float*)d_in[13];
    const float* alpha1 = (const float*)d_in[14];
    const float* beta1  = (const float*)d_in[15];
    const float* alpha2 = (const float*)d_in[16];
    const float* beta2  = (const float*)d_in[17];
    float* out = (float*)d_out;

    float *xn, *q, *k, *v, *ctx, *x1, *ff;
    cudaGetSymbolAddress((void**)&xn,  g_xn);
    cudaGetSymbolAddress((void**)&q,   g_q);
    cudaGetSymbolAddress((void**)&k,   g_k);
    cudaGetSymbolAddress((void**)&v,   g_v);
    cudaGetSymbolAddress((void**)&ctx, g_ctx);
    cudaGetSymbolAddress((void**)&x1,  g_x1);
    cudaGetSymbolAddress((void**)&ff,  g_ff);

    cudaFuncSetAttribute(attention_kernel,
                         cudaFuncAttributeMaxDynamicSharedMemorySize,
                         ATT_SMEM_BYTES);

    // 1) xn = LN(x, alpha1, beta1)
    layernorm_kernel<<<ROWS, 256>>>(x, xn, alpha1, beta1);

    // 2) q,k,v = (xn @ w{q,k,v} + b) scattered to [B,H,S,DK]
    dim3 gqkv(DD / GBN, ROWS / GBM);
    sgemm_f32x2<1><<<gqkv, 256>>>(xn, wq, bq, nullptr, q, ROWS, DD, DD);
    sgemm_f32x2<1><<<gqkv, 256>>>(xn, wk, bk, nullptr, k, ROWS, DD, DD);
    sgemm_f32x2<1><<<gqkv, 256>>>(xn, wv, bv, nullptr, v, ROWS, DD, DD);

    // 3) attention -> ctx [B,S,D]
    attention_kernel<<<dim3(SS / 64, BB * HH), 256, ATT_SMEM_BYTES>>>(q, k, v, mask, ctx);

    // 4) x1 = x + ctx @ wo + bo
    sgemm_f32x2<2><<<dim3(DD / GBN, ROWS / GBM), 256>>>(ctx, wo, bo, x, x1, ROWS, DD, DD);

    // 5) xn2 = LN(x1, alpha2, beta2)  (reuse g_xn)
    layernorm_kernel<<<ROWS, 256>>>(x1, xn, alpha2, beta2);

    // 6) ff = relu(xn2 @ w1 + b1)
    sgemm_f32x2<3><<<dim3(DFF_ / GBN, ROWS / GBM), 256>>>(xn, w1, b1, nullptr, ff, ROWS, DFF_, DD);

    // 7) out = x1 + ff @ w2 + b2
    sgemm_f32x2<2><<<dim3(DD / GBN, ROWS / GBM), 256>>>(ff, w2, b2, x1, out, ROWS, DD, DFF_);
}

// round 13
// speedup vs baseline: 2.0982x; 2.0982x over previous
#include <cuda_runtime.h>
#include <cuda_bf16.h>
#include <cstdint>
#include <cstddef>

// ============================================================================
// Problem constants: B=4, S=1024, D=1024, H=16, DK=64, DFF=4096
// ============================================================================
#define BB   4
#define SS   1024
#define DD   1024
#define HH   16
#define DKK  64
#define DFF_ 4096
#define ROWS (BB * SS)   // 4096

// ---------------------------------------------------------------------------
// Scratch: __device__ globals (no cudaMalloc allowed)
// ---------------------------------------------------------------------------
__device__ __nv_bfloat16 g_xnh [ROWS * DD];
__device__ __nv_bfloat16 g_xnl [ROWS * DD];
__device__ float         g_q   [ROWS * DD];     // [B,H,S,DK]
__device__ float         g_k   [ROWS * DD];
__device__ float         g_v   [ROWS * DD];
__device__ __nv_bfloat16 g_ctxh[ROWS * DD];
__device__ __nv_bfloat16 g_ctxl[ROWS * DD];
__device__ float         g_x1  [ROWS * DD];
__device__ __nv_bfloat16 g_ffh [(size_t)ROWS * DFF_];
__device__ __nv_bfloat16 g_ffl [(size_t)ROWS * DFF_];
// transposed+split weights [N,K] K-major: wq@0, wk@1M, wv@2M, wo@3M, w1t@4M, w2t@8M
__device__ __nv_bfloat16 g_wth [12 * 1024 * 1024];
__device__ __nv_bfloat16 g_wtl [12 * 1024 * 1024];

// ---------------------------------------------------------------------------
// PTX helpers (all plain-sm_103-legal: cp.async, ldmatrix, mma.sync bf16)
// ---------------------------------------------------------------------------
__device__ __forceinline__ uint32_t smem_u32(const void* p) {
    uint32_t a;
    asm("{ .reg .u64 t; cvta.to.shared.u64 t, %1; cvt.u32.u64 %0, t; }"
        : "=r"(a) : "l"(p));
    return a;
}
__device__ __forceinline__ void cp_async16(uint32_t dst, const void* src) {
    asm volatile("cp.async.cg.shared.global [%0], [%1], 16;"
                 :: "r"(dst), "l"(src) : "memory");
}
#define CP_COMMIT() asm volatile("cp.async.commit_group;" ::: "memory")

__device__ __forceinline__ void ldm_x4(uint32_t* r, uint32_t addr) {
    asm volatile("ldmatrix.sync.aligned.m8n8.x4.shared.b16 {%0,%1,%2,%3}, [%4];"
                 : "=r"(r[0]), "=r"(r[1]), "=r"(r[2]), "=r"(r[3]) : "r"(addr));
}
__device__ __forceinline__ void mma_bf16(float* c, const uint32_t* a,
                                         uint32_t b0, uint32_t b1) {
    asm volatile(
        "mma.sync.aligned.m16n8k16.row.col.f32.bf16.bf16.f32 "
        "{%0,%1,%2,%3}, {%4,%5,%6,%7}, {%8,%9}, {%0,%1,%2,%3};"
        : "+f"(c[0]), "+f"(c[1]), "+f"(c[2]), "+f"(c[3])
        : "r"(a[0]), "r"(a[1]), "r"(a[2]), "r"(a[3]), "r"(b0), "r"(b1));
}

__device__ __forceinline__ void split_bf16(float x, __nv_bfloat16& hi, __nv_bfloat16& lo) {
    hi = __float2bfloat16(x);
    lo = __float2bfloat16(x - __bfloat162float(hi));
}

// ============================================================================
// LayerNorm -> bf16 hi/lo split output
// ============================================================================
__global__ void __launch_bounds__(256)
layernorm_bf16(const float* __restrict__ x,
               __nv_bfloat16* __restrict__ oh, __nv_bfloat16* __restrict__ ol,
               const float* __restrict__ alpha, const float* __restrict__ beta)
{
    __shared__ float red[16];
    const int row = blockIdx.x;
    const int tid = threadIdx.x;
    const float* xr = x + (size_t)row * DD;

    float4 v = *(const float4*)(xr + tid * 4);
    float s = v.x + v.y + v.z + v.w;
    #pragma unroll
    for (int o = 16; o > 0; o >>= 1) s += __shfl_xor_sync(0xffffffffu, s, o);
    if ((tid & 31) == 0) red[tid >> 5] = s;
    __syncthreads();
    float tot = red[0] + red[1] + red[2] + red[3] + red[4] + red[5] + red[6] + red[7];
    float mean = tot * (1.0f / (float)DD);

    float dx0 = v.x - mean, dx1 = v.y - mean, dx2 = v.z - mean, dx3 = v.w - mean;
    float q = dx0 * dx0 + dx1 * dx1 + dx2 * dx2 + dx3 * dx3;
    #pragma unroll
    for (int o = 16; o > 0; o >>= 1) q += __shfl_xor_sync(0xffffffffu, q, o);
    if ((tid & 31) == 0) red[8 + (tid >> 5)] = q;
    __syncthreads();
    float ssq = red[8] + red[9] + red[10] + red[11] + red[12] + red[13] + red[14] + red[15];

    float stdv = sqrtf(ssq * (1.0f / (float)(DD - 1)));
    float a = __ldg(alpha), b = __ldg(beta);
    float r = a / (stdv + 1e-6f);

    float y[4] = {dx0 * r + b, dx1 * r + b, dx2 * r + b, dx3 * r + b};
    __nv_bfloat16 h[4], l[4];
    #pragma unroll
    for (int i = 0; i < 4; i++) split_bf16(y[i], h[i], l[i]);
    size_t o0 = (size_t)row * DD + tid * 4;
    __nv_bfloat162 h01; h01.x = h[0]; h01.y = h[1];
    __nv_bfloat162 h23; h23.x = h[2]; h23.y = h[3];
    __nv_bfloat162 l01; l01.x = l[0]; l01.y = l[1];
    __nv_bfloat162 l23; l23.x = l[2]; l23.y = l[3];
    *(__nv_bfloat162*)(oh + o0)     = h01;
    *(__nv_bfloat162*)(oh + o0 + 2) = h23;
    *(__nv_bfloat162*)(ol + o0)     = l01;
    *(__nv_bfloat162*)(ol + o0 + 2) = l23;
}

// ============================================================================
// Weight transpose + bf16 split:  W[K,N] fp32 -> Wt_hi/Wt_lo [N,K] bf16
// ============================================================================
__global__ void __launch_bounds__(256)
wconv_kernel(const float* __restrict__ W,
             __nv_bfloat16* __restrict__ Th, __nv_bfloat16* __restrict__ Tl,
             int K, int N)
{
    __shared__ float t[32][33];
    const int n0 = blockIdx.x * 32, k0 = blockIdx.y * 32;
    const int tx = threadIdx.x, ty = threadIdx.y;
    #pragma unroll
    for (int r = 0; r < 4; r++) {
        int k = k0 + ty + r * 8;
        t[ty + r * 8][tx] = W[(size_t)k * N + n0 + tx];
    }
    __syncthreads();
    #pragma unroll
    for (int r = 0; r < 4; r++) {
        int n = n0 + ty + r * 8;
        int k = k0 + tx;
        float x = t[tx][ty + r * 8];
        __nv_bfloat16 hi, lo;
        split_bf16(x, hi, lo);
        Th[(size_t)n * K + k] = hi;
        Tl[(size_t)n * K + k] = lo;
    }
}

// ============================================================================
// HMMA bf16-split GEMM: C[M,N] = (Ah+Al)[M,K] @ (Bh+Bl)[N,K]^T (3 products)
// CTA 128x128, K-chunk 32, 8 warps (warp tile 32x64), 3-stage cp.async.
// SMEM rows: 32 bf16 = 64B data, 80B stride (conflict-free ldmatrix).
// MODE 1: +bias, scatter to [B,H,S,DK] fp32
// MODE 2: +bias +res, fp32
// MODE 3: +bias, ReLU, hi/lo bf16
// ============================================================================
#define BKC     32
#define ROWB    80
#define TILE_B  (128 * ROWB)      // 10240
#define STAGE_B (4 * TILE_B)      // 40960  (Ah, Al, Bh, Bl)
#define NSTAGE  3
#define GEMM_SMEM (NSTAGE * STAGE_B + 512 + 128)

__device__ __forceinline__ void load_tile32(uint32_t tb, const __nv_bfloat16* src,
                                            int rowBase, int K, int kc, int tid)
{
    #pragma unroll
    for (int j = 0; j < 2; j++) {
        int u = tid + j * 256;           // 0..511
        int row = u >> 2, c = u & 3;
        cp_async16(tb + row * ROWB + c * 16,
                   src + (size_t)(rowBase + row) * K + kc + c * 8);
    }
}

template<int MODE>
__global__ void __launch_bounds__(256, 1)
hgemm(const __nv_bfloat16* __restrict__ Ah, const __nv_bfloat16* __restrict__ Al,
      const __nv_bfloat16* __restrict__ Bh, const __nv_bfloat16* __restrict__ Bl,
      const float* __restrict__ bias, const float* __restrict__ res,
      float* __restrict__ out,
      __nv_bfloat16* __restrict__ outh, __nv_bfloat16* __restrict__ outl,
      int M, int N, int K)
{
    extern __shared__ char smem[];
    const uint32_t raw = smem_u32(smem);
    const uint32_t sb  = (raw + 127u) & ~127u;
    float* sBias = (float*)(smem + (sb - raw) + NSTAGE * STAGE_B);

    const int tid  = threadIdx.x;
    const int wid  = tid >> 5, lane = tid & 31;
    const int wm   = wid & 3;          // m offset 32*wm
    const int wn   = wid >> 2;         // n offset 64*wn
    const int m0   = blockIdx.y * 128, n0 = blockIdx.x * 128;
    const int T    = K / BKC;

    if (tid < 128) sBias[tid] = bias[n0 + tid];

    float acc[2][8][4];
    #pragma unroll
    for (int a = 0; a < 2; a++)
        #pragma unroll
        for (int b = 0; b < 8; b++)
            #pragma unroll
            for (int c = 0; c < 4; c++) acc[a][b][c] = 0.0f;

    // prologue: chunks 0..NSTAGE-2
    #pragma unroll
    for (int p = 0; p < NSTAGE - 1; p++) {
        uint32_t st = sb + p * STAGE_B;
        load_tile32(st,              Ah, m0, K, p * BKC, tid);
        load_tile32(st + TILE_B,     Al, m0, K, p * BKC, tid);
        load_tile32(st + 2 * TILE_B, Bh, n0, K, p * BKC, tid);
        load_tile32(st + 3 * TILE_B, Bl, n0, K, p * BKC, tid);
        CP_COMMIT();
    }

    const uint32_t lrow = lane & 15, lhalf = lane >> 4;

    for (int t = 0; t < T; t++) {
        asm volatile("cp.async.wait_group %0;" :: "n"(NSTAGE - 2) : "memory");
        __syncthreads();

        // issue loads for chunk t+NSTAGE-1 (into buffer consumed at iter t-1)
        {
            const int tn = t + NSTAGE - 1;
            if (tn < T) {
                uint32_t st = sb + (tn % NSTAGE) * STAGE_B;
                const int kc = tn * BKC;
                load_tile32(st,              Ah, m0, K, kc, tid);
                load_tile32(st + TILE_B,     Al, m0, K, kc, tid);
                load_tile32(st + 2 * TILE_B, Bh, n0, K, kc, tid);
                load_tile32(st + 3 * TILE_B, Bl, n0, K, kc, tid);
            }
            CP_COMMIT();
        }

        const uint32_t st = sb + (t % NSTAGE) * STAGE_B;
        #pragma unroll
        for (int ks = 0; ks < 2; ks++) {
            const uint32_t aoff = (wm * 32 + lrow) * ROWB + lhalf * 16 + ks * 32;
            uint32_t ah[2][4], al[2][4];
            ldm_x4(ah[0], st + aoff);
            ldm_x4(ah[1], st + aoff + 16 * ROWB);
            ldm_x4(al[0], st + TILE_B + aoff);
            ldm_x4(al[1], st + TILE_B + aoff + 16 * ROWB);

            const uint32_t boff = (wn * 64 + lrow) * ROWB + lhalf * 16 + ks * 32;
            uint32_t bh[4][4], bl[4][4];
            #pragma unroll
            for (int nt = 0; nt < 4; nt++) {
                ldm_x4(bh[nt], st + 2 * TILE_B + boff + nt * 16 * ROWB);
                ldm_x4(bl[nt], st + 3 * TILE_B + boff + nt * 16 * ROWB);
            }

            #pragma unroll
            for (int mt = 0; mt < 2; mt++) {
                #pragma unroll
                for (int nt = 0; nt < 4; nt++) {
                    // n-tile halves: {r0,r2} = n0-7, {r1,r3} = n8-15
                    mma_bf16(acc[mt][2 * nt],     ah[mt], bh[nt][0], bh[nt][2]);
                    mma_bf16(acc[mt][2 * nt + 1], ah[mt], bh[nt][1], bh[nt][3]);
                    mma_bf16(acc[mt][2 * nt],     ah[mt], bl[nt][0], bl[nt][2]);
                    mma_bf16(acc[mt][2 * nt + 1], ah[mt], bl[nt][1], bl[nt][3]);
                    mma_bf16(acc[mt][2 * nt],     al[mt], bh[nt][0], bh[nt][2]);
                    mma_bf16(acc[mt][2 * nt + 1], al[mt], bh[nt][1], bh[nt][3]);
                }
            }
        }
    }

    // ---- epilogue: fragment (mt, jn): c0,c1 @ (m=g, n=2q), c2,c3 @ m=g+8 ----
    const int g = lane >> 2, qd = lane & 3;
    #pragma unroll
    for (int mt = 0; mt < 2; mt++) {
        #pragma unroll
        for (int jn = 0; jn < 8; jn++) {
            const int gm = m0 + wm * 32 + mt * 16 + g;
            const int gn = n0 + wn * 64 + jn * 8 + qd * 2;
            const float b0 = sBias[gn - n0], b1 = sBias[gn - n0 + 1];
            float v0 = acc[mt][jn][0] + b0;
            float v1 = acc[mt][jn][1] + b1;
            float v2 = acc[mt][jn][2] + b0;
            float v3 = acc[mt][jn][3] + b1;

            if (MODE == 1) {
                const int b_ = gm >> 10, s = gm & 1023;
                const int h_ = gn >> 6,  dk = gn & 63;
                float* o0 = out + (((size_t)(b_ * HH + h_) * SS + s) << 6) + dk;
                o0[0] = v0; o0[1] = v1;
                const int b2_ = (gm + 8) >> 10, s2 = (gm + 8) & 1023;
                float* o1 = out + (((size_t)(b2_ * HH + h_) * SS + s2) << 6) + dk;
                o1[0] = v2; o1[1] = v3;
            } else if (MODE == 2) {
                float2 r0 = *(const float2*)(res + (size_t)gm * N + gn);
                float2 r1 = *(const float2*)(res + (size_t)(gm + 8) * N + gn);
                *(float2*)(out + (size_t)gm * N + gn)       = make_float2(v0 + r0.x, v1 + r0.y);
                *(float2*)(out + (size_t)(gm + 8) * N + gn) = make_float2(v2 + r1.x, v3 + r1.y);
            } else {  // MODE 3
                v0 = fmaxf(v0, 0.0f); v1 = fmaxf(v1, 0.0f);
                v2 = fmaxf(v2, 0.0f); v3 = fmaxf(v3, 0.0f);
                __nv_bfloat16 h0, l0, h1, l1;
                split_bf16(v0, h0, l0); split_bf16(v1, h1, l1);
                __nv_bfloat162 hh; hh.x = h0; hh.y = h1;
                __nv_bfloat162 ll; ll.x = l0; ll.y = l1;
                *(__nv_bfloat162*)(outh + (size_t)gm * N + gn) = hh;
                *(__nv_bfloat162*)(outl + (size_t)gm * N + gn) = ll;
                split_bf16(v2, h0, l0); split_bf16(v3, h1, l1);
                hh.x = h0; hh.y = h1; ll.x = l0; ll.y = l1;
                *(__nv_bfloat162*)(outh + (size_t)(gm + 8) * N + gn) = hh;
                *(__nv_bfloat162*)(outl + (size_t)(gm + 8) * N + gn) = ll;
            }
        }
    }
}

// ============================================================================
// Flash attention, fp32 -> ctx as bf16 hi/lo. (unchanged from passing R9)
// ============================================================================
#define ATT_STRIDE 68
#define ATT_SMEM_BYTES (4 * 64 * ATT_STRIDE * (int)sizeof(float))

__global__ void __launch_bounds__(256)
attention_kernel(const float* __restrict__ q, const float* __restrict__ k,
                 const float* __restrict__ v, const int* __restrict__ mask,
                 __nv_bfloat16* __restrict__ ctxh, __nv_bfloat16* __restrict__ ctxl)
{
    extern __shared__ float sm[];
    float* Qs = sm;
    float* Ks = sm + 64 * ATT_STRIDE;
    float* Vs = sm + 2 * 64 * ATT_STRIDE;
    float* Ps = sm + 3 * 64 * ATT_STRIDE;

    const int tid = threadIdx.x;
    const int ty = tid >> 4, tx = tid & 15;
    const int bh = blockIdx.y;
    const int b  = bh >> 4, h = bh & 15;
    const int q0 = blockIdx.x * 64;

    const float* qb = q + (size_t)bh * (SS * DKK);
    const float* kb = k + (size_t)bh * (SS * DKK);
    const float* vb = v + (size_t)bh * (SS * DKK);

    #pragma unroll
    for (int r = 0; r < 4; r++) {
        int idx = tid + r * 256;
        int s = idx >> 4, c4 = idx & 15;
        float4 t = *(const float4*)(qb + (size_t)(q0 + s) * DKK + c4 * 4);
        Qs[(c4 * 4 + 0) * ATT_STRIDE + s] = t.x * 0.125f;
        Qs[(c4 * 4 + 1) * ATT_STRIDE + s] = t.y * 0.125f;
        Qs[(c4 * 4 + 2) * ATT_STRIDE + s] = t.z * 0.125f;
        Qs[(c4 * 4 + 3) * ATT_STRIDE + s] = t.w * 0.125f;
    }

    float m_run[4], l_run[4], acc[4][4];
    #pragma unroll
    for (int i = 0; i < 4; i++) {
        m_run[i] = -1e30f; l_run[i] = 0.0f;
        #pragma unroll
        for (int j = 0; j < 4; j++) acc[i][j] = 0.0f;
    }

    for (int kt = 0; kt < 16; kt++) {
        __syncthreads();
        #pragma unroll
        for (int r = 0; r < 4; r++) {
            int idx = tid + r * 256;
            int s = idx >> 4, c4 = idx & 15;
            float4 tk = *(const float4*)(kb + (size_t)(kt * 64 + s) * DKK + c4 * 4);
            Ks[(c4 * 4 + 0) * ATT_STRIDE + s] = tk.x;
            Ks[(c4 * 4 + 1) * ATT_STRIDE + s] = tk.y;
            Ks[(c4 * 4 + 2) * ATT_STRIDE + s] = tk.z;
            Ks[(c4 * 4 + 3) * ATT_STRIDE + s] = tk.w;
            float4 tv = *(const float4*)(vb + (size_t)(kt * 64 + s) * DKK + c4 * 4);
            *(float4*)&Vs[s * ATT_STRIDE + c4 * 4] = tv;
        }
        __syncthreads();

        float sc[4][4];
        #pragma unroll
        for (int i = 0; i < 4; i++)
            #pragma unroll
            for (int j = 0; j < 4; j++) sc[i][j] = 0.0f;

        #pragma unroll 16
        for (int kk = 0; kk < 64; kk++) {
            float4 qv = *(const float4*)&Qs[kk * ATT_STRIDE + ty * 4];
            float4 kv = *(const float4*)&Ks[kk * ATT_STRIDE + tx * 4];
            float qa[4] = {qv.x, qv.y, qv.z, qv.w};
            #pragma unroll
            for (int i = 0; i < 4; i++) {
                sc[i][0] += qa[i] * kv.x;
                sc[i][1] += qa[i] * kv.y;
                sc[i][2] += qa[i] * kv.z;
                sc[i][3] += qa[i] * kv.w;
            }
        }

        const int key0 = kt * 64 + tx * 4;
        #pragma unroll
        for (int j = 0; j < 4; j++) {
            if (__ldg(mask + b * SS + key0 + j) == 0) {
                sc[0][j] = -1e9f; sc[1][j] = -1e9f; sc[2][j] = -1e9f; sc[3][j] = -1e9f;
            }
        }

        #pragma unroll
        for (int i = 0; i < 4; i++) {
            float mt = fmaxf(fmaxf(sc[i][0], sc[i][1]), fmaxf(sc[i][2], sc[i][3]));
            mt = fmaxf(mt, __shfl_xor_sync(0xffffffffu, mt, 1, 16));
            mt = fmaxf(mt, __shfl_xor_sync(0xffffffffu, mt, 2, 16));
            mt = fmaxf(mt, __shfl_xor_sync(0xffffffffu, mt, 4, 16));
            mt = fmaxf(mt, __shfl_xor_sync(0xffffffffu, mt, 8, 16));
            float mn   = fmaxf(m_run[i], mt);
            float corr = __expf(m_run[i] - mn);
            m_run[i] = mn;
            float rs = 0.0f;
            #pragma unroll
            for (int j = 0; j < 4; j++) { sc[i][j] = __expf(sc[i][j] - mn); rs += sc[i][j]; }
            rs += __shfl_xor_sync(0xffffffffu, rs, 1, 16);
            rs += __shfl_xor_sync(0xffffffffu, rs, 2, 16);
            rs += __shfl_xor_sync(0xffffffffu, rs, 4, 16);
            rs += __shfl_xor_sync(0xffffffffu, rs, 8, 16);
            l_run[i] = l_run[i] * corr + rs;
            #pragma unroll
            for (int j = 0; j < 4; j++) acc[i][j] *= corr;
            *(float4*)&Ps[(ty * 4 + i) * ATT_STRIDE + tx * 4] =
                make_float4(sc[i][0], sc[i][1], sc[i][2], sc[i][3]);
        }
        __syncthreads();

        #pragma unroll 8
        for (int c = 0; c < 64; c++) {
            float4 vv = *(const float4*)&Vs[c * ATT_STRIDE + tx * 4];
            #pragma unroll
            for (int i = 0; i < 4; i++) {
                float p = Ps[(ty * 4 + i) * ATT_STRIDE + c];
                acc[i][0] += p * vv.x;
                acc[i][1] += p * vv.y;
                acc[i][2] += p * vv.z;
                acc[i][3] += p * vv.w;
            }
        }
    }

    #pragma unroll
    for (int i = 0; i < 4; i++) {
        float rinv = __fdividef(1.0f, l_run[i]);
        int s = q0 + ty * 4 + i;
        float o[4] = {acc[i][0] * rinv, acc[i][1] * rinv,
                      acc[i][2] * rinv, acc[i][3] * rinv};
        __nv_bfloat16 hh[4], ll[4];
        #pragma unroll
        for (int j = 0; j < 4; j++) split_bf16(o[j], hh[j], ll[j]);
        size_t base = ((size_t)(b * SS + s)) * DD + h * DKK + tx * 4;
        __nv_bfloat162 h01; h01.x = hh[0]; h01.y = hh[1];
        __nv_bfloat162 h23; h23.x = hh[2]; h23.y = hh[3];
        __nv_bfloat162 l01; l01.x = ll[0]; l01.y = ll[1];
        __nv_bfloat162 l23; l23.x = ll[2]; l23.y = ll[3];
        *(__nv_bfloat162*)(ctxh + base)     = h01;
        *(__nv_bfloat162*)(ctxh + base + 2) = h23;
        *(__nv_bfloat162*)(ctxl + base)     = l01;
        *(__nv_bfloat162*)(ctxl + base + 2) = l23;
    }
}

// ============================================================================
// Launch
// ============================================================================
extern "C" void kernel_launch(void* const* d_in, const int* in_sizes, int n_in,
                              void* d_out, int out_size)
{
    const float* x      = (const float*)d_in[0];
    const int*   mask   = (const int*)  d_in[1];
    const float* wq     = (const float*)d_in[2];
    const float* bq     = (const float*)d_in[3];
    const float* wk     = (const float*)d_in[4];
    const float* bk     = (const float*)d_in[5];
    const float* wv     = (const float*)d_in[6];
    const float* bv     = (const float*)d_in[7];
    const float* wo     = (const float*)d_in[8];
    const float* bo     = (const float*)d_in[9];
    const float* w1     = (const float*)d_in[10];
    const float* b1     = (const float*)d_in[11];
    const float* w2     = (const float*)d_in[12];
    const float* b2     = (const float*)d_in[13];
    const float* alpha1 = (const float*)d_in[14];
    const float* beta1  = (const float*)d_in[15];
    const float* alpha2 = (const float*)d_in[16];
    const float* beta2  = (const float*)d_in[17];
    float* out = (float*)d_out;

    __nv_bfloat16 *xnh, *xnl, *ctxh, *ctxl, *ffh, *ffl, *wth, *wtl;
    float *q, *k, *v, *x1;
    cudaGetSymbolAddress((void**)&xnh,  g_xnh);
    cudaGetSymbolAddress((void**)&xnl,  g_xnl);
    cudaGetSymbolAddress((void**)&q,    g_q);
    cudaGetSymbolAddress((void**)&k,    g_k);
    cudaGetSymbolAddress((void**)&v,    g_v);
    cudaGetSymbolAddress((void**)&ctxh, g_ctxh);
    cudaGetSymbolAddress((void**)&ctxl, g_ctxl);
    cudaGetSymbolAddress((void**)&x1,   g_x1);
    cudaGetSymbolAddress((void**)&ffh,  g_ffh);
    cudaGetSymbolAddress((void**)&ffl,  g_ffl);
    cudaGetSymbolAddress((void**)&wth,  g_wth);
    cudaGetSymbolAddress((void**)&wtl,  g_wtl);

    cudaFuncSetAttribute(hgemm<1>, cudaFuncAttributeMaxDynamicSharedMemorySize, GEMM_SMEM);
    cudaFuncSetAttribute(hgemm<2>, cudaFuncAttributeMaxDynamicSharedMemorySize, GEMM_SMEM);
    cudaFuncSetAttribute(hgemm<3>, cudaFuncAttributeMaxDynamicSharedMemorySize, GEMM_SMEM);
    cudaFuncSetAttribute(attention_kernel, cudaFuncAttributeMaxDynamicSharedMemorySize, ATT_SMEM_BYTES);

    const size_t MEG = 1024 * 1024;

    // ---- weight transpose + split ----
    wconv_kernel<<<dim3(DD / 32, DD / 32),   dim3(32, 8)>>>(wq, wth + 0 * MEG, wtl + 0 * MEG, DD,  DD);
    wconv_kernel<<<dim3(DD / 32, DD / 32),   dim3(32, 8)>>>(wk, wth + 1 * MEG, wtl + 1 * MEG, DD,  DD);
    wconv_kernel<<<dim3(DD / 32, DD / 32),   dim3(32, 8)>>>(wv, wth + 2 * MEG, wtl + 2 * MEG, DD,  DD);
    wconv_kernel<<<dim3(DD / 32, DD / 32),   dim3(32, 8)>>>(wo, wth + 3 * MEG, wtl + 3 * MEG, DD,  DD);
    wconv_kernel<<<dim3(DFF_ / 32, DD / 32), dim3(32, 8)>>>(w1, wth + 4 * MEG, wtl + 4 * MEG, DD,  DFF_);
    wconv_kernel<<<dim3(DD / 32, DFF_ / 32), dim3(32, 8)>>>(w2, wth + 8 * MEG, wtl + 8 * MEG, DFF_, DD);

    // 1) xn = LN(x) -> hi/lo bf16
    layernorm_bf16<<<ROWS, 256>>>(x, xnh, xnl, alpha1, beta1);

    // 2) q,k,v GEMMs (scatter [B,H,S,DK] fp32)
    dim3 gqkv(DD / 128, ROWS / 128);
    hgemm<1><<<gqkv, 256, GEMM_SMEM>>>(xnh, xnl, wth + 0 * MEG, wtl + 0 * MEG, bq, nullptr, q, nullptr, nullptr, ROWS, DD, DD);
    hgemm<1><<<gqkv, 256, GEMM_SMEM>>>(xnh, xnl, wth + 1 * MEG, wtl + 1 * MEG, bk, nullptr, k, nullptr, nullptr, ROWS, DD, DD);
    hgemm<1><<<gqkv, 256, GEMM_SMEM>>>(xnh, xnl, wth + 2 * MEG, wtl + 2 * MEG, bv, nullptr, v, nullptr, nullptr, ROWS, DD, DD);

    // 3) attention -> ctx hi/lo bf16
    attention_kernel<<<dim3(SS / 64, BB * HH), 256, ATT_SMEM_BYTES>>>(q, k, v, mask, ctxh, ctxl);

    // 4) x1 = x + ctx @ wo + bo
    hgemm<2><<<gqkv, 256, GEMM_SMEM>>>(ctxh, ctxl, wth + 3 * MEG, wtl + 3 * MEG, bo, x, x1, nullptr, nullptr, ROWS, DD, DD);

    // 5) xn2 = LN(x1)
    layernorm_bf16<<<ROWS, 256>>>(x1, xnh, xnl, alpha2, beta2);

    // 6) ff = relu(xn2 @ w1 + b1) -> hi/lo bf16
    hgemm<3><<<dim3(DFF_ / 128, ROWS / 128), 256, GEMM_SMEM>>>(xnh, xnl, wth + 4 * MEG, wtl + 4 * MEG, b1, nullptr, nullptr, ffh, ffl, ROWS, DFF_, DD);

    // 7) out = x1 + ff @ w2 + b2
    hgemm<2><<<dim3(DD / 128, ROWS / 128), 256, GEMM_SMEM>>>(ffh, ffl, wth + 8 * MEG, wtl + 8 * MEG, b2, x1, out, nullptr, nullptr, ROWS, DD, DFF_);
}

// round 14
// speedup vs baseline: 2.0995x; 1.0006x over previous
#include <cuda_runtime.h>
#include <cuda_bf16.h>
#include <cstdint>
#include <cstddef>

// ============================================================================
// Problem constants: B=4, S=1024, D=1024, H=16, DK=64, DFF=4096
// ============================================================================
#define BB   4
#define SS   1024
#define DD   1024
#define HH   16
#define DKK  64
#define DFF_ 4096
#define ROWS (BB * SS)   // 4096

// ---------------------------------------------------------------------------
// Scratch: __device__ globals (no cudaMalloc allowed)
// ---------------------------------------------------------------------------
__device__ __nv_bfloat16 g_xnh [ROWS * DD];
__device__ __nv_bfloat16 g_xnl [ROWS * DD];
__device__ float         g_q   [ROWS * DD];     // [B,H,S,DK]
__device__ float         g_k   [ROWS * DD];
__device__ float         g_v   [ROWS * DD];
__device__ __nv_bfloat16 g_ctxh[ROWS * DD];
__device__ __nv_bfloat16 g_ctxl[ROWS * DD];
__device__ float         g_x1  [ROWS * DD];
__device__ __nv_bfloat16 g_ffh [(size_t)ROWS * DFF_];
__device__ __nv_bfloat16 g_ffl [(size_t)ROWS * DFF_];
// transposed+split weights [N,K] K-major: wq@0, wk@1M, wv@2M, wo@3M, w1t@4M, w2t@8M
__device__ __nv_bfloat16 g_wth [12 * 1024 * 1024];
__device__ __nv_bfloat16 g_wtl [12 * 1024 * 1024];

// ---------------------------------------------------------------------------
// PTX helpers (all plain-sm_103-legal: cp.async, ldmatrix, mma.sync bf16)
// ---------------------------------------------------------------------------
__device__ __forceinline__ uint32_t smem_u32(const void* p) {
    uint32_t a;
    asm("{ .reg .u64 t; cvta.to.shared.u64 t, %1; cvt.u32.u64 %0, t; }"
        : "=r"(a) : "l"(p));
    return a;
}
__device__ __forceinline__ void cp_async16(uint32_t dst, const void* src) {
    asm volatile("cp.async.cg.shared.global [%0], [%1], 16;"
                 :: "r"(dst), "l"(src) : "memory");
}
#define CP_COMMIT() asm volatile("cp.async.commit_group;" ::: "memory")

__device__ __forceinline__ void ldm_x4(uint32_t* r, uint32_t addr) {
    asm volatile("ldmatrix.sync.aligned.m8n8.x4.shared.b16 {%0,%1,%2,%3}, [%4];"
                 : "=r"(r[0]), "=r"(r[1]), "=r"(r[2]), "=r"(r[3]) : "r"(addr));
}
__device__ __forceinline__ void mma_bf16(float* c, const uint32_t* a,
                                         uint32_t b0, uint32_t b1) {
    asm volatile(
        "mma.sync.aligned.m16n8k16.row.col.f32.bf16.bf16.f32 "
        "{%0,%1,%2,%3}, {%4,%5,%6,%7}, {%8,%9}, {%0,%1,%2,%3};"
        : "+f"(c[0]), "+f"(c[1]), "+f"(c[2]), "+f"(c[3])
        : "r"(a[0]), "r"(a[1]), "r"(a[2]), "r"(a[3]), "r"(b0), "r"(b1));
}

__device__ __forceinline__ void split_bf16(float x, __nv_bfloat16& hi, __nv_bfloat16& lo) {
    hi = __float2bfloat16(x);
    lo = __float2bfloat16(x - __bfloat162float(hi));
}

// ============================================================================
// LayerNorm -> bf16 hi/lo split output
// ============================================================================
__global__ void __launch_bounds__(256)
layernorm_bf16(const float* __restrict__ x,
               __nv_bfloat16* __restrict__ oh, __nv_bfloat16* __restrict__ ol,
               const float* __restrict__ alpha, const float* __restrict__ beta)
{
    __shared__ float red[16];
    const int row = blockIdx.x;
    const int tid = threadIdx.x;
    const float* xr = x + (size_t)row * DD;

    float4 v = *(const float4*)(xr + tid * 4);
    float s = v.x + v.y + v.z + v.w;
    #pragma unroll
    for (int o = 16; o > 0; o >>= 1) s += __shfl_xor_sync(0xffffffffu, s, o);
    if ((tid & 31) == 0) red[tid >> 5] = s;
    __syncthreads();
    float tot = red[0] + red[1] + red[2] + red[3] + red[4] + red[5] + red[6] + red[7];
    float mean = tot * (1.0f / (float)DD);

    float dx0 = v.x - mean, dx1 = v.y - mean, dx2 = v.z - mean, dx3 = v.w - mean;
    float q = dx0 * dx0 + dx1 * dx1 + dx2 * dx2 + dx3 * dx3;
    #pragma unroll
    for (int o = 16; o > 0; o >>= 1) q += __shfl_xor_sync(0xffffffffu, q, o);
    if ((tid & 31) == 0) red[8 + (tid >> 5)] = q;
    __syncthreads();
    float ssq = red[8] + red[9] + red[10] + red[11] + red[12] + red[13] + red[14] + red[15];

    float stdv = sqrtf(ssq * (1.0f / (float)(DD - 1)));
    float a = __ldg(alpha), b = __ldg(beta);
    float r = a / (stdv + 1e-6f);

    float y[4] = {dx0 * r + b, dx1 * r + b, dx2 * r + b, dx3 * r + b};
    __nv_bfloat16 h[4], l[4];
    #pragma unroll
    for (int i = 0; i < 4; i++) split_bf16(y[i], h[i], l[i]);
    size_t o0 = (size_t)row * DD + tid * 4;
    __nv_bfloat162 h01; h01.x = h[0]; h01.y = h[1];
    __nv_bfloat162 h23; h23.x = h[2]; h23.y = h[3];
    __nv_bfloat162 l01; l01.x = l[0]; l01.y = l[1];
    __nv_bfloat162 l23; l23.x = l[2]; l23.y = l[3];
    *(__nv_bfloat162*)(oh + o0)     = h01;
    *(__nv_bfloat162*)(oh + o0 + 2) = h23;
    *(__nv_bfloat162*)(ol + o0)     = l01;
    *(__nv_bfloat162*)(ol + o0 + 2) = l23;
}

// ============================================================================
// Weight transpose + bf16 split:  W[K,N] fp32 -> Wt_hi/Wt_lo [N,K] bf16
// ============================================================================
__global__ void __launch_bounds__(256)
wconv_kernel(const float* __restrict__ W,
             __nv_bfloat16* __restrict__ Th, __nv_bfloat16* __restrict__ Tl,
             int K, int N)
{
    __shared__ float t[32][33];
    const int n0 = blockIdx.x * 32, k0 = blockIdx.y * 32;
    const int tx = threadIdx.x, ty = threadIdx.y;
    #pragma unroll
    for (int r = 0; r < 4; r++) {
        int k = k0 + ty + r * 8;
        t[ty + r * 8][tx] = W[(size_t)k * N + n0 + tx];
    }
    __syncthreads();
    #pragma unroll
    for (int r = 0; r < 4; r++) {
        int n = n0 + ty + r * 8;
        int k = k0 + tx;
        float x = t[tx][ty + r * 8];
        __nv_bfloat16 hi, lo;
        split_bf16(x, hi, lo);
        Th[(size_t)n * K + k] = hi;
        Tl[(size_t)n * K + k] = lo;
    }
}

// ============================================================================
// HMMA bf16-split GEMM: C[M,N] = (Ah+Al)[M,K] @ (Bh+Bl)[N,K]^T (3 products)
// CTA 128x128, K-chunk 32, 8 warps (warp tile 32x64), 3-stage cp.async.
// SMEM rows: 32 bf16 = 64B data, 80B stride (conflict-free ldmatrix).
// MODE 1: +bias, scatter to [B,H,S,DK] fp32
// MODE 2: +bias +res, fp32
// MODE 3: +bias, ReLU, hi/lo bf16
// ============================================================================
#define BKC     32
#define ROWB    80
#define TILE_B  (128 * ROWB)      // 10240
#define STAGE_B (4 * TILE_B)      // 40960  (Ah, Al, Bh, Bl)
#define NSTAGE  3
#define GEMM_SMEM (NSTAGE * STAGE_B + 512 + 128)

__device__ __forceinline__ void load_tile32(uint32_t tb, const __nv_bfloat16* src,
                                            int rowBase, int K, int kc, int tid)
{
    #pragma unroll
    for (int j = 0; j < 2; j++) {
        int u = tid + j * 256;           // 0..511
        int row = u >> 2, c = u & 3;
        cp_async16(tb + row * ROWB + c * 16,
                   src + (size_t)(rowBase + row) * K + kc + c * 8);
    }
}

template<int MODE>
__global__ void __launch_bounds__(256, 1)
hgemm(const __nv_bfloat16* __restrict__ Ah, const __nv_bfloat16* __restrict__ Al,
      const __nv_bfloat16* __restrict__ Bh, const __nv_bfloat16* __restrict__ Bl,
      const float* __restrict__ bias, const float* __restrict__ res,
      float* __restrict__ out,
      __nv_bfloat16* __restrict__ outh, __nv_bfloat16* __restrict__ outl,
      int M, int N, int K)
{
    extern __shared__ char smem[];
    const uint32_t raw = smem_u32(smem);
    const uint32_t sb  = (raw + 127u) & ~127u;
    float* sBias = (float*)(smem + (sb - raw) + NSTAGE * STAGE_B);

    const int tid  = threadIdx.x;
    const int wid  = tid >> 5, lane = tid & 31;
    const int wm   = wid & 3;          // m offset 32*wm
    const int wn   = wid >> 2;         // n offset 64*wn
    const int m0   = blockIdx.y * 128, n0 = blockIdx.x * 128;
    const int T    = K / BKC;

    if (tid < 128) sBias[tid] = bias[n0 + tid];

    float acc[2][8][4];
    #pragma unroll
    for (int a = 0; a < 2; a++)
        #pragma unroll
        for (int b = 0; b < 8; b++)
            #pragma unroll
            for (int c = 0; c < 4; c++) acc[a][b][c] = 0.0f;

    // prologue: chunks 0..NSTAGE-2
    #pragma unroll
    for (int p = 0; p < NSTAGE - 1; p++) {
        uint32_t st = sb + p * STAGE_B;
        load_tile32(st,              Ah, m0, K, p * BKC, tid);
        load_tile32(st + TILE_B,     Al, m0, K, p * BKC, tid);
        load_tile32(st + 2 * TILE_B, Bh, n0, K, p * BKC, tid);
        load_tile32(st + 3 * TILE_B, Bl, n0, K, p * BKC, tid);
        CP_COMMIT();
    }

    const uint32_t lrow = lane & 15, lhalf = lane >> 4;

    for (int t = 0; t < T; t++) {
        asm volatile("cp.async.wait_group %0;" :: "n"(NSTAGE - 2) : "memory");
        __syncthreads();

        // issue loads for chunk t+NSTAGE-1 (into buffer consumed at iter t-1)
        {
            const int tn = t + NSTAGE - 1;
            if (tn < T) {
                uint32_t st = sb + (tn % NSTAGE) * STAGE_B;
                const int kc = tn * BKC;
                load_tile32(st,              Ah, m0, K, kc, tid);
                load_tile32(st + TILE_B,     Al, m0, K, kc, tid);
                load_tile32(st + 2 * TILE_B, Bh, n0, K, kc, tid);
                load_tile32(st + 3 * TILE_B, Bl, n0, K, kc, tid);
            }
            CP_COMMIT();
        }

        const uint32_t st = sb + (t % NSTAGE) * STAGE_B;
        #pragma unroll
        for (int ks = 0; ks < 2; ks++) {
            const uint32_t aoff = (wm * 32 + lrow) * ROWB + lhalf * 16 + ks * 32;
            uint32_t ah[2][4], al[2][4];
            ldm_x4(ah[0], st + aoff);
            ldm_x4(ah[1], st + aoff + 16 * ROWB);
            ldm_x4(al[0], st + TILE_B + aoff);
            ldm_x4(al[1], st + TILE_B + aoff + 16 * ROWB);

            const uint32_t boff = (wn * 64 + lrow) * ROWB + lhalf * 16 + ks * 32;
            uint32_t bh[4][4], bl[4][4];
            #pragma unroll
            for (int nt = 0; nt < 4; nt++) {
                ldm_x4(bh[nt], st + 2 * TILE_B + boff + nt * 16 * ROWB);
                ldm_x4(bl[nt], st + 3 * TILE_B + boff + nt * 16 * ROWB);
            }

            #pragma unroll
            for (int mt = 0; mt < 2; mt++) {
                #pragma unroll
                for (int nt = 0; nt < 4; nt++) {
                    // n-tile halves: {r0,r2} = n0-7, {r1,r3} = n8-15
                    mma_bf16(acc[mt][2 * nt],     ah[mt], bh[nt][0], bh[nt][2]);
                    mma_bf16(acc[mt][2 * nt + 1], ah[mt], bh[nt][1], bh[nt][3]);
                    mma_bf16(acc[mt][2 * nt],     ah[mt], bl[nt][0], bl[nt][2]);
                    mma_bf16(acc[mt][2 * nt + 1], ah[mt], bl[nt][1], bl[nt][3]);
                    mma_bf16(acc[mt][2 * nt],     al[mt], bh[nt][0], bh[nt][2]);
                    mma_bf16(acc[mt][2 * nt + 1], al[mt], bh[nt][1], bh[nt][3]);
                }
            }
        }
    }

    // ---- epilogue: fragment (mt, jn): c0,c1 @ (m=g, n=2q), c2,c3 @ m=g+8 ----
    const int g = lane >> 2, qd = lane & 3;
    #pragma unroll
    for (int mt = 0; mt < 2; mt++) {
        #pragma unroll
        for (int jn = 0; jn < 8; jn++) {
            const int gm = m0 + wm * 32 + mt * 16 + g;
            const int gn = n0 + wn * 64 + jn * 8 + qd * 2;
            const float b0 = sBias[gn - n0], b1 = sBias[gn - n0 + 1];
            float v0 = acc[mt][jn][0] + b0;
            float v1 = acc[mt][jn][1] + b1;
            float v2 = acc[mt][jn][2] + b0;
            float v3 = acc[mt][jn][3] + b1;

            if (MODE == 1) {
                const int b_ = gm >> 10, s = gm & 1023;
                const int h_ = gn >> 6,  dk = gn & 63;
                float* o0 = out + (((size_t)(b_ * HH + h_) * SS + s) << 6) + dk;
                o0[0] = v0; o0[1] = v1;
                const int b2_ = (gm + 8) >> 10, s2 = (gm + 8) & 1023;
                float* o1 = out + (((size_t)(b2_ * HH + h_) * SS + s2) << 6) + dk;
                o1[0] = v2; o1[1] = v3;
            } else if (MODE == 2) {
                float2 r0 = *(const float2*)(res + (size_t)gm * N + gn);
                float2 r1 = *(const float2*)(res + (size_t)(gm + 8) * N + gn);
                *(float2*)(out + (size_t)gm * N + gn)       = make_float2(v0 + r0.x, v1 + r0.y);
                *(float2*)(out + (size_t)(gm + 8) * N + gn) = make_float2(v2 + r1.x, v3 + r1.y);
            } else {  // MODE 3
                v0 = fmaxf(v0, 0.0f); v1 = fmaxf(v1, 0.0f);
                v2 = fmaxf(v2, 0.0f); v3 = fmaxf(v3, 0.0f);
                __nv_bfloat16 h0, l0, h1, l1;
                split_bf16(v0, h0, l0); split_bf16(v1, h1, l1);
                __nv_bfloat162 hh; hh.x = h0; hh.y = h1;
                __nv_bfloat162 ll; ll.x = l0; ll.y = l1;
                *(__nv_bfloat162*)(outh + (size_t)gm * N + gn) = hh;
                *(__nv_bfloat162*)(outl + (size_t)gm * N + gn) = ll;
                split_bf16(v2, h0, l0); split_bf16(v3, h1, l1);
                hh.x = h0; hh.y = h1; ll.x = l0; ll.y = l1;
                *(__nv_bfloat162*)(outh + (size_t)(gm + 8) * N + gn) = hh;
                *(__nv_bfloat162*)(outl + (size_t)(gm + 8) * N + gn) = ll;
            }
        }
    }
}

// ============================================================================
// Flash attention, fp32 -> ctx as bf16 hi/lo. (unchanged from passing R9)
// ============================================================================
#define ATT_STRIDE 68
#define ATT_SMEM_BYTES (4 * 64 * ATT_STRIDE * (int)sizeof(float))

__global__ void __launch_bounds__(256)
attention_kernel(const float* __restrict__ q, const float* __restrict__ k,
                 const float* __restrict__ v, const int* __restrict__ mask,
                 __nv_bfloat16* __restrict__ ctxh, __nv_bfloat16* __restrict__ ctxl)
{
    extern __shared__ float sm[];
    float* Qs = sm;
    float* Ks = sm + 64 * ATT_STRIDE;
    float* Vs = sm + 2 * 64 * ATT_STRIDE;
    float* Ps = sm + 3 * 64 * ATT_STRIDE;

    const int tid = threadIdx.x;
    const int ty = tid >> 4, tx = tid & 15;
    const int bh = blockIdx.y;
    const int b  = bh >> 4, h = bh & 15;
    const int q0 = blockIdx.x * 64;

    const float* qb = q + (size_t)bh * (SS * DKK);
    const float* kb = k + (size_t)bh * (SS * DKK);
    const float* vb = v + (size_t)bh * (SS * DKK);

    #pragma unroll
    for (int r = 0; r < 4; r++) {
        int idx = tid + r * 256;
        int s = idx >> 4, c4 = idx & 15;
        float4 t = *(const float4*)(qb + (size_t)(q0 + s) * DKK + c4 * 4);
        Qs[(c4 * 4 + 0) * ATT_STRIDE + s] = t.x * 0.125f;
        Qs[(c4 * 4 + 1) * ATT_STRIDE + s] = t.y * 0.125f;
        Qs[(c4 * 4 + 2) * ATT_STRIDE + s] = t.z * 0.125f;
        Qs[(c4 * 4 + 3) * ATT_STRIDE + s] = t.w * 0.125f;
    }

    float m_run[4], l_run[4], acc[4][4];
    #pragma unroll
    for (int i = 0; i < 4; i++) {
        m_run[i] = -1e30f; l_run[i] = 0.0f;
        #pragma unroll
        for (int j = 0; j < 4; j++) acc[i][j] = 0.0f;
    }

    for (int kt = 0; kt < 16; kt++) {
        __syncthreads();
        #pragma unroll
        for (int r = 0; r < 4; r++) {
            int idx = tid + r * 256;
            int s = idx >> 4, c4 = idx & 15;
            float4 tk = *(const float4*)(kb + (size_t)(kt * 64 + s) * DKK + c4 * 4);
            Ks[(c4 * 4 + 0) * ATT_STRIDE + s] = tk.x;
            Ks[(c4 * 4 + 1) * ATT_STRIDE + s] = tk.y;
            Ks[(c4 * 4 + 2) * ATT_STRIDE + s] = tk.z;
            Ks[(c4 * 4 + 3) * ATT_STRIDE + s] = tk.w;
            float4 tv = *(const float4*)(vb + (size_t)(kt * 64 + s) * DKK + c4 * 4);
            *(float4*)&Vs[s * ATT_STRIDE + c4 * 4] = tv;
        }
        __syncthreads();

        float sc[4][4];
        #pragma unroll
        for (int i = 0; i < 4; i++)
            #pragma unroll
            for (int j = 0; j < 4; j++) sc[i][j] = 0.0f;

        #pragma unroll 16
        for (int kk = 0; kk < 64; kk++) {
            float4 qv = *(const float4*)&Qs[kk * ATT_STRIDE + ty * 4];
            float4 kv = *(const float4*)&Ks[kk * ATT_STRIDE + tx * 4];
            float qa[4] = {qv.x, qv.y, qv.z, qv.w};
            #pragma unroll
            for (int i = 0; i < 4; i++) {
                sc[i][0] += qa[i] * kv.x;
                sc[i][1] += qa[i] * kv.y;
                sc[i][2] += qa[i] * kv.z;
                sc[i][3] += qa[i] * kv.w;
            }
        }

        const int key0 = kt * 64 + tx * 4;
        #pragma unroll
        for (int j = 0; j < 4; j++) {
            if (__ldg(mask + b * SS + key0 + j) == 0) {
                sc[0][j] = -1e9f; sc[1][j] = -1e9f; sc[2][j] = -1e9f; sc[3][j] = -1e9f;
            }
        }

        #pragma unroll
        for (int i = 0; i < 4; i++) {
            float mt = fmaxf(fmaxf(sc[i][0], sc[i][1]), fmaxf(sc[i][2], sc[i][3]));
            mt = fmaxf(mt, __shfl_xor_sync(0xffffffffu, mt, 1, 16));
            mt = fmaxf(mt, __shfl_xor_sync(0xffffffffu, mt, 2, 16));
            mt = fmaxf(mt, __shfl_xor_sync(0xffffffffu, mt, 4, 16));
            mt = fmaxf(mt, __shfl_xor_sync(0xffffffffu, mt, 8, 16));
            float mn   = fmaxf(m_run[i], mt);
            float corr = __expf(m_run[i] - mn);
            m_run[i] = mn;
            float rs = 0.0f;
            #pragma unroll
            for (int j = 0; j < 4; j++) { sc[i][j] = __expf(sc[i][j] - mn); rs += sc[i][j]; }
            rs += __shfl_xor_sync(0xffffffffu, rs, 1, 16);
            rs += __shfl_xor_sync(0xffffffffu, rs, 2, 16);
            rs += __shfl_xor_sync(0xffffffffu, rs, 4, 16);
            rs += __shfl_xor_sync(0xffffffffu, rs, 8, 16);
            l_run[i] = l_run[i] * corr + rs;
            #pragma unroll
            for (int j = 0; j < 4; j++) acc[i][j] *= corr;
            *(float4*)&Ps[(ty * 4 + i) * ATT_STRIDE + tx * 4] =
                make_float4(sc[i][0], sc[i][1], sc[i][2], sc[i][3]);
        }
        __syncthreads();

        #pragma unroll 8
        for (int c = 0; c < 64; c++) {
            float4 vv = *(const float4*)&Vs[c * ATT_STRIDE + tx * 4];
            #pragma unroll
            for (int i = 0; i < 4; i++) {
                float p = Ps[(ty * 4 + i) * ATT_STRIDE + c];
                acc[i][0] += p * vv.x;
                acc[i][1] += p * vv.y;
                acc[i][2] += p * vv.z;
                acc[i][3] += p * vv.w;
            }
        }
    }

    #pragma unroll
    for (int i = 0; i < 4; i++) {
        float rinv = __fdividef(1.0f, l_run[i]);
        int s = q0 + ty * 4 + i;
        float o[4] = {acc[i][0] * rinv, acc[i][1] * rinv,
                      acc[i][2] * rinv, acc[i][3] * rinv};
        __nv_bfloat16 hh[4], ll[4];
        #pragma unroll
        for (int j = 0; j < 4; j++) split_bf16(o[j], hh[j], ll[j]);
        size_t base = ((size_t)(b * SS + s)) * DD + h * DKK + tx * 4;
        __nv_bfloat162 h01; h01.x = hh[0]; h01.y = hh[1];
        __nv_bfloat162 h23; h23.x = hh[2]; h23.y = hh[3];
        __nv_bfloat162 l01; l01.x = ll[0]; l01.y = ll[1];
        __nv_bfloat162 l23; l23.x = ll[2]; l23.y = ll[3];
        *(__nv_bfloat162*)(ctxh + base)     = h01;
        *(__nv_bfloat162*)(ctxh + base + 2) = h23;
        *(__nv_bfloat162*)(ctxl + base)     = l01;
        *(__nv_bfloat162*)(ctxl + base + 2) = l23;
    }
}

// ============================================================================
// Launch
// ============================================================================
extern "C" void kernel_launch(void* const* d_in, const int* in_sizes, int n_in,
                              void* d_out, int out_size)
{
    const float* x      = (const float*)d_in[0];
    const int*   mask   = (const int*)  d_in[1];
    const float* wq     = (const float*)d_in[2];
    const float* bq     = (const float*)d_in[3];
    const float* wk     = (const float*)d_in[4];
    const float* bk     = (const float*)d_in[5];
    const float* wv     = (const float*)d_in[6];
    const float* bv     = (const float*)d_in[7];
    const float* wo     = (const float*)d_in[8];
    const float* bo     = (const float*)d_in[9];
    const float* w1     = (const float*)d_in[10];
    const float* b1     = (const float*)d_in[11];
    const float* w2     = (const float*)d_in[12];
    const float* b2     = (const float*)d_in[13];
    const float* alpha1 = (const float*)d_in[14];
    const float* beta1  = (const float*)d_in[15];
    const float* alpha2 = (const float*)d_in[16];
    const float* beta2  = (const float*)d_in[17];
    float* out = (float*)d_out;

    __nv_bfloat16 *xnh, *xnl, *ctxh, *ctxl, *ffh, *ffl, *wth, *wtl;
    float *q, *k, *v, *x1;
    cudaGetSymbolAddress((void**)&xnh,  g_xnh);
    cudaGetSymbolAddress((void**)&xnl,  g_xnl);
    cudaGetSymbolAddress((void**)&q,    g_q);
    cudaGetSymbolAddress((void**)&k,    g_k);
    cudaGetSymbolAddress((void**)&v,    g_v);
    cudaGetSymbolAddress((void**)&ctxh, g_ctxh);
    cudaGetSymbolAddress((void**)&ctxl, g_ctxl);
    cudaGetSymbolAddress((void**)&x1,   g_x1);
    cudaGetSymbolAddress((void**)&ffh,  g_ffh);
    cudaGetSymbolAddress((void**)&ffl,  g_ffl);
    cudaGetSymbolAddress((void**)&wth,  g_wth);
    cudaGetSymbolAddress((void**)&wtl,  g_wtl);

    cudaFuncSetAttribute(hgemm<1>, cudaFuncAttributeMaxDynamicSharedMemorySize, GEMM_SMEM);
    cudaFuncSetAttribute(hgemm<2>, cudaFuncAttributeMaxDynamicSharedMemorySize, GEMM_SMEM);
    cudaFuncSetAttribute(hgemm<3>, cudaFuncAttributeMaxDynamicSharedMemorySize, GEMM_SMEM);
    cudaFuncSetAttribute(attention_kernel, cudaFuncAttributeMaxDynamicSharedMemorySize, ATT_SMEM_BYTES);

    const size_t MEG = 1024 * 1024;

    // ---- weight transpose + split ----
    wconv_kernel<<<dim3(DD / 32, DD / 32),   dim3(32, 8)>>>(wq, wth + 0 * MEG, wtl + 0 * MEG, DD,  DD);
    wconv_kernel<<<dim3(DD / 32, DD / 32),   dim3(32, 8)>>>(wk, wth + 1 * MEG, wtl + 1 * MEG, DD,  DD);
    wconv_kernel<<<dim3(DD / 32, DD / 32),   dim3(32, 8)>>>(wv, wth + 2 * MEG, wtl + 2 * MEG, DD,  DD);
    wconv_kernel<<<dim3(DD / 32, DD / 32),   dim3(32, 8)>>>(wo, wth + 3 * MEG, wtl + 3 * MEG, DD,  DD);
    wconv_kernel<<<dim3(DFF_ / 32, DD / 32), dim3(32, 8)>>>(w1, wth + 4 * MEG, wtl + 4 * MEG, DD,  DFF_);
    wconv_kernel<<<dim3(DD / 32, DFF_ / 32), dim3(32, 8)>>>(w2, wth + 8 * MEG, wtl + 8 * MEG, DFF_, DD);

    // 1) xn = LN(x) -> hi/lo bf16
    layernorm_bf16<<<ROWS, 256>>>(x, xnh, xnl, alpha1, beta1);

    // 2) q,k,v GEMMs (scatter [B,H,S,DK] fp32)
    dim3 gqkv(DD / 128, ROWS / 128);
    hgemm<1><<<gqkv, 256, GEMM_SMEM>>>(xnh, xnl, wth + 0 * MEG, wtl + 0 * MEG, bq, nullptr, q, nullptr, nullptr, ROWS, DD, DD);
    hgemm<1><<<gqkv, 256, GEMM_SMEM>>>(xnh, xnl, wth + 1 * MEG, wtl + 1 * MEG, bk, nullptr, k, nullptr, nullptr, ROWS, DD, DD);
    hgemm<1><<<gqkv, 256, GEMM_SMEM>>>(xnh, xnl, wth + 2 * MEG, wtl + 2 * MEG, bv, nullptr, v, nullptr, nullptr, ROWS, DD, DD);

    // 3) attention -> ctx hi/lo bf16
    attention_kernel<<<dim3(SS / 64, BB * HH), 256, ATT_SMEM_BYTES>>>(q, k, v, mask, ctxh, ctxl);

    // 4) x1 = x + ctx @ wo + bo
    hgemm<2><<<gqkv, 256, GEMM_SMEM>>>(ctxh, ctxl, wth + 3 * MEG, wtl + 3 * MEG, bo, x, x1, nullptr, nullptr, ROWS, DD, DD);

    // 5) xn2 = LN(x1)
    layernorm_bf16<<<ROWS, 256>>>(x1, xnh, xnl, alpha2, beta2);

    // 6) ff = relu(xn2 @ w1 + b1) -> hi/lo bf16
    hgemm<3><<<dim3(DFF_ / 128, ROWS / 128), 256, GEMM_SMEM>>>(xnh, xnl, wth + 4 * MEG, wtl + 4 * MEG, b1, nullptr, nullptr, ffh, ffl, ROWS, DFF_, DD);

    // 7) out = x1 + ff @ w2 + b2
    hgemm<2><<<dim3(DD / 128, ROWS / 128), 256, GEMM_SMEM>>>(ffh, ffl, wth + 8 * MEG, wtl + 8 * MEG, b2, x1, out, nullptr, nullptr, ROWS, DD, DFF_);
}

// round 15
// speedup vs baseline: 2.5893x; 1.2333x over previous
#include <cuda_runtime.h>
#include <cuda_bf16.h>
#include <cstdint>
#include <cstddef>

// ============================================================================
// Problem constants: B=4, S=1024, D=1024, H=16, DK=64, DFF=4096
// ============================================================================
#define BB   4
#define SS   1024
#define DD   1024
#define HH   16
#define DKK  64
#define DFF_ 4096
#define ROWS (BB * SS)   // 4096

// ---------------------------------------------------------------------------
// Scratch: __device__ globals (no cudaMalloc allowed)
// ---------------------------------------------------------------------------
__device__ __nv_bfloat16 g_xnh [ROWS * DD];
__device__ __nv_bfloat16 g_xnl [ROWS * DD];
__device__ __nv_bfloat16 g_qh  [ROWS * DD];     // [B,H,S,DK] bf16 hi/lo
__device__ __nv_bfloat16 g_ql  [ROWS * DD];
__device__ __nv_bfloat16 g_kh  [ROWS * DD];
__device__ __nv_bfloat16 g_kl  [ROWS * DD];
__device__ __nv_bfloat16 g_vh  [ROWS * DD];
__device__ __nv_bfloat16 g_vl  [ROWS * DD];
__device__ __nv_bfloat16 g_ctxh[ROWS * DD];
__device__ __nv_bfloat16 g_ctxl[ROWS * DD];
__device__ float         g_x1  [ROWS * DD];
__device__ __nv_bfloat16 g_ffh [(size_t)ROWS * DFF_];
__device__ __nv_bfloat16 g_ffl [(size_t)ROWS * DFF_];
// transposed+split weights [N,K] K-major: wq@0, wk@1M, wv@2M, wo@3M, w1t@4M, w2t@8M
__device__ __nv_bfloat16 g_wth [12 * 1024 * 1024];
__device__ __nv_bfloat16 g_wtl [12 * 1024 * 1024];

// ---------------------------------------------------------------------------
// PTX helpers (all plain-sm_103-legal: cp.async, ldmatrix, mma.sync bf16)
// ---------------------------------------------------------------------------
__device__ __forceinline__ uint32_t smem_u32(const void* p) {
    uint32_t a;
    asm("{ .reg .u64 t; cvta.to.shared.u64 t, %1; cvt.u32.u64 %0, t; }"
        : "=r"(a) : "l"(p));
    return a;
}
__device__ __forceinline__ void cp_async16(uint32_t dst, const void* src) {
    asm volatile("cp.async.cg.shared.global [%0], [%1], 16;"
                 :: "r"(dst), "l"(src) : "memory");
}
#define CP_COMMIT() asm volatile("cp.async.commit_group;" ::: "memory")

__device__ __forceinline__ void ldm_x4(uint32_t* r, uint32_t addr) {
    asm volatile("ldmatrix.sync.aligned.m8n8.x4.shared.b16 {%0,%1,%2,%3}, [%4];"
                 : "=r"(r[0]), "=r"(r[1]), "=r"(r[2]), "=r"(r[3]) : "r"(addr));
}
__device__ __forceinline__ void ldm_x4_t(uint32_t* r, uint32_t addr) {
    asm volatile("ldmatrix.sync.aligned.m8n8.x4.trans.shared.b16 {%0,%1,%2,%3}, [%4];"
                 : "=r"(r[0]), "=r"(r[1]), "=r"(r[2]), "=r"(r[3]) : "r"(addr));
}
__device__ __forceinline__ void mma_bf16(float* c, const uint32_t* a,
                                         uint32_t b0, uint32_t b1) {
    asm volatile(
        "mma.sync.aligned.m16n8k16.row.col.f32.bf16.bf16.f32 "
        "{%0,%1,%2,%3}, {%4,%5,%6,%7}, {%8,%9}, {%0,%1,%2,%3};"
        : "+f"(c[0]), "+f"(c[1]), "+f"(c[2]), "+f"(c[3])
        : "r"(a[0]), "r"(a[1]), "r"(a[2]), "r"(a[3]), "r"(b0), "r"(b1));
}

__device__ __forceinline__ void split_bf16(float x, __nv_bfloat16& hi, __nv_bfloat16& lo) {
    hi = __float2bfloat16(x);
    lo = __float2bfloat16(x - __bfloat162float(hi));
}
// pack two floats into hi/lo bf16x2 words (x -> low half)
__device__ __forceinline__ void pack_split2(float x, float y,
                                            uint32_t& hw, uint32_t& lw) {
    __nv_bfloat162 h, l;
    h.x = __float2bfloat16(x);
    h.y = __float2bfloat16(y);
    l.x = __float2bfloat16(x - __bfloat162float(h.x));
    l.y = __float2bfloat16(y - __bfloat162float(h.y));
    hw = *(uint32_t*)&h;
    lw = *(uint32_t*)&l;
}

// ============================================================================
// LayerNorm -> bf16 hi/lo split output
// ============================================================================
__global__ void __launch_bounds__(256)
layernorm_bf16(const float* __restrict__ x,
               __nv_bfloat16* __restrict__ oh, __nv_bfloat16* __restrict__ ol,
               const float* __restrict__ alpha, const float* __restrict__ beta)
{
    __shared__ float red[16];
    const int row = blockIdx.x;
    const int tid = threadIdx.x;
    const float* xr = x + (size_t)row * DD;

    float4 v = *(const float4*)(xr + tid * 4);
    float s = v.x + v.y + v.z + v.w;
    #pragma unroll
    for (int o = 16; o > 0; o >>= 1) s += __shfl_xor_sync(0xffffffffu, s, o);
    if ((tid & 31) == 0) red[tid >> 5] = s;
    __syncthreads();
    float tot = red[0] + red[1] + red[2] + red[3] + red[4] + red[5] + red[6] + red[7];
    float mean = tot * (1.0f / (float)DD);

    float dx0 = v.x - mean, dx1 = v.y - mean, dx2 = v.z - mean, dx3 = v.w - mean;
    float q = dx0 * dx0 + dx1 * dx1 + dx2 * dx2 + dx3 * dx3;
    #pragma unroll
    for (int o = 16; o > 0; o >>= 1) q += __shfl_xor_sync(0xffffffffu, q, o);
    if ((tid & 31) == 0) red[8 + (tid >> 5)] = q;
    __syncthreads();
    float ssq = red[8] + red[9] + red[10] + red[11] + red[12] + red[13] + red[14] + red[15];

    float stdv = sqrtf(ssq * (1.0f / (float)(DD - 1)));
    float a = __ldg(alpha), b = __ldg(beta);
    float r = a / (stdv + 1e-6f);

    float y[4] = {dx0 * r + b, dx1 * r + b, dx2 * r + b, dx3 * r + b};
    uint32_t h01, l01, h23, l23;
    pack_split2(y[0], y[1], h01, l01);
    pack_split2(y[2], y[3], h23, l23);
    size_t o0 = (size_t)row * DD + tid * 4;
    *(uint32_t*)(oh + o0)     = h01;
    *(uint32_t*)(oh + o0 + 2) = h23;
    *(uint32_t*)(ol + o0)     = l01;
    *(uint32_t*)(ol + o0 + 2) = l23;
}

// ============================================================================
// Weight transpose + bf16 split:  W[K,N] fp32 -> Wt_hi/Wt_lo [N,K] bf16
// ============================================================================
__global__ void __launch_bounds__(256)
wconv_kernel(const float* __restrict__ W,
             __nv_bfloat16* __restrict__ Th, __nv_bfloat16* __restrict__ Tl,
             int K, int N)
{
    __shared__ float t[32][33];
    const int n0 = blockIdx.x * 32, k0 = blockIdx.y * 32;
    const int tx = threadIdx.x, ty = threadIdx.y;
    #pragma unroll
    for (int r = 0; r < 4; r++) {
        int k = k0 + ty + r * 8;
        t[ty + r * 8][tx] = W[(size_t)k * N + n0 + tx];
    }
    __syncthreads();
    #pragma unroll
    for (int r = 0; r < 4; r++) {
        int n = n0 + ty + r * 8;
        int k = k0 + tx;
        float x = t[tx][ty + r * 8];
        __nv_bfloat16 hi, lo;
        split_bf16(x, hi, lo);
        Th[(size_t)n * K + k] = hi;
        Tl[(size_t)n * K + k] = lo;
    }
}

// ============================================================================
// HMMA bf16-split GEMM (as R14). MODE 1: bf16 hi/lo scatter [B,H,S,DK] *scale
//                                 MODE 2: +res fp32   MODE 3: ReLU bf16 hi/lo
// ============================================================================
#define BKC     32
#define ROWB    80
#define TILE_B  (128 * ROWB)
#define STAGE_B (4 * TILE_B)
#define NSTAGE  3
#define GEMM_SMEM (NSTAGE * STAGE_B + 512 + 128)

__device__ __forceinline__ void load_tile32(uint32_t tb, const __nv_bfloat16* src,
                                            int rowBase, int K, int kc, int tid)
{
    #pragma unroll
    for (int j = 0; j < 2; j++) {
        int u = tid + j * 256;
        int row = u >> 2, c = u & 3;
        cp_async16(tb + row * ROWB + c * 16,
                   src + (size_t)(rowBase + row) * K + kc + c * 8);
    }
}

template<int MODE>
__global__ void __launch_bounds__(256, 1)
hgemm(const __nv_bfloat16* __restrict__ Ah, const __nv_bfloat16* __restrict__ Al,
      const __nv_bfloat16* __restrict__ Bh, const __nv_bfloat16* __restrict__ Bl,
      const float* __restrict__ bias, const float* __restrict__ res,
      float* __restrict__ out,
      __nv_bfloat16* __restrict__ outh, __nv_bfloat16* __restrict__ outl,
      int M, int N, int K, float scale)
{
    extern __shared__ char smem[];
    const uint32_t raw = smem_u32(smem);
    const uint32_t sb  = (raw + 127u) & ~127u;
    float* sBias = (float*)(smem + (sb - raw) + NSTAGE * STAGE_B);

    const int tid  = threadIdx.x;
    const int wid  = tid >> 5, lane = tid & 31;
    const int wm   = wid & 3;
    const int wn   = wid >> 2;
    const int m0   = blockIdx.y * 128, n0 = blockIdx.x * 128;
    const int T    = K / BKC;

    if (tid < 128) sBias[tid] = bias[n0 + tid];

    float acc[2][8][4];
    #pragma unroll
    for (int a = 0; a < 2; a++)
        #pragma unroll
        for (int b = 0; b < 8; b++)
            #pragma unroll
            for (int c = 0; c < 4; c++) acc[a][b][c] = 0.0f;

    #pragma unroll
    for (int p = 0; p < NSTAGE - 1; p++) {
        uint32_t st = sb + p * STAGE_B;
        load_tile32(st,              Ah, m0, K, p * BKC, tid);
        load_tile32(st + TILE_B,     Al, m0, K, p * BKC, tid);
        load_tile32(st + 2 * TILE_B, Bh, n0, K, p * BKC, tid);
        load_tile32(st + 3 * TILE_B, Bl, n0, K, p * BKC, tid);
        CP_COMMIT();
    }

    const uint32_t lrow = lane & 15, lhalf = lane >> 4;

    for (int t = 0; t < T; t++) {
        asm volatile("cp.async.wait_group %0;" :: "n"(NSTAGE - 2) : "memory");
        __syncthreads();

        {
            const int tn = t + NSTAGE - 1;
            if (tn < T) {
                uint32_t st = sb + (tn % NSTAGE) * STAGE_B;
                const int kc = tn * BKC;
                load_tile32(st,              Ah, m0, K, kc, tid);
                load_tile32(st + TILE_B,     Al, m0, K, kc, tid);
                load_tile32(st + 2 * TILE_B, Bh, n0, K, kc, tid);
                load_tile32(st + 3 * TILE_B, Bl, n0, K, kc, tid);
            }
            CP_COMMIT();
        }

        const uint32_t st = sb + (t % NSTAGE) * STAGE_B;
        #pragma unroll
        for (int ks = 0; ks < 2; ks++) {
            const uint32_t aoff = (wm * 32 + lrow) * ROWB + lhalf * 16 + ks * 32;
            uint32_t ah[2][4], al[2][4];
            ldm_x4(ah[0], st + aoff);
            ldm_x4(ah[1], st + aoff + 16 * ROWB);
            ldm_x4(al[0], st + TILE_B + aoff);
            ldm_x4(al[1], st + TILE_B + aoff + 16 * ROWB);

            const uint32_t boff = (wn * 64 + lrow) * ROWB + lhalf * 16 + ks * 32;
            uint32_t bh[4][4], bl[4][4];
            #pragma unroll
            for (int nt = 0; nt < 4; nt++) {
                ldm_x4(bh[nt], st + 2 * TILE_B + boff + nt * 16 * ROWB);
                ldm_x4(bl[nt], st + 3 * TILE_B + boff + nt * 16 * ROWB);
            }

            #pragma unroll
            for (int mt = 0; mt < 2; mt++) {
                #pragma unroll
                for (int nt = 0; nt < 4; nt++) {
                    mma_bf16(acc[mt][2 * nt],     ah[mt], bh[nt][0], bh[nt][2]);
                    mma_bf16(acc[mt][2 * nt + 1], ah[mt], bh[nt][1], bh[nt][3]);
                    mma_bf16(acc[mt][2 * nt],     ah[mt], bl[nt][0], bl[nt][2]);
                    mma_bf16(acc[mt][2 * nt + 1], ah[mt], bl[nt][1], bl[nt][3]);
                    mma_bf16(acc[mt][2 * nt],     al[mt], bh[nt][0], bh[nt][2]);
                    mma_bf16(acc[mt][2 * nt + 1], al[mt], bh[nt][1], bh[nt][3]);
                }
            }
        }
    }

    const int g = lane >> 2, qd = lane & 3;
    #pragma unroll
    for (int mt = 0; mt < 2; mt++) {
        #pragma unroll
        for (int jn = 0; jn < 8; jn++) {
            const int gm = m0 + wm * 32 + mt * 16 + g;
            const int gn = n0 + wn * 64 + jn * 8 + qd * 2;
            const float b0 = sBias[gn - n0], b1 = sBias[gn - n0 + 1];
            float v0 = acc[mt][jn][0] + b0;
            float v1 = acc[mt][jn][1] + b1;
            float v2 = acc[mt][jn][2] + b0;
            float v3 = acc[mt][jn][3] + b1;

            if (MODE == 1) {
                v0 *= scale; v1 *= scale; v2 *= scale; v3 *= scale;
                const int h_ = gn >> 6, dk = gn & 63;
                const int b_  = gm >> 10,       s  = gm & 1023;
                const int b2_ = (gm + 8) >> 10, s2 = (gm + 8) & 1023;
                size_t i0 = (((size_t)(b_  * HH + h_) * SS + s ) << 6) + dk;
                size_t i1 = (((size_t)(b2_ * HH + h_) * SS + s2) << 6) + dk;
                uint32_t hw, lw;
                pack_split2(v0, v1, hw, lw);
                *(uint32_t*)(outh + i0) = hw; *(uint32_t*)(outl + i0) = lw;
                pack_split2(v2, v3, hw, lw);
                *(uint32_t*)(outh + i1) = hw; *(uint32_t*)(outl + i1) = lw;
            } else if (MODE == 2) {
                float2 r0 = *(const float2*)(res + (size_t)gm * N + gn);
                float2 r1 = *(const float2*)(res + (size_t)(gm + 8) * N + gn);
                *(float2*)(out + (size_t)gm * N + gn)       = make_float2(v0 + r0.x, v1 + r0.y);
                *(float2*)(out + (size_t)(gm + 8) * N + gn) = make_float2(v2 + r1.x, v3 + r1.y);
            } else {
                v0 = fmaxf(v0, 0.0f); v1 = fmaxf(v1, 0.0f);
                v2 = fmaxf(v2, 0.0f); v3 = fmaxf(v3, 0.0f);
                uint32_t hw, lw;
                pack_split2(v0, v1, hw, lw);
                *(uint32_t*)(outh + (size_t)gm * N + gn) = hw;
                *(uint32_t*)(outl + (size_t)gm * N + gn) = lw;
                pack_split2(v2, v3, hw, lw);
                *(uint32_t*)(outh + (size_t)(gm + 8) * N + gn) = hw;
                *(uint32_t*)(outl + (size_t)(gm + 8) * N + gn) = lw;
            }
        }
    }
}

// ============================================================================
// HMMA flash attention. CTA = 128 q-rows x (b,h); 8 warps, warp = m16.
// S = (Qh+Ql)(Kh+Kl)^T 3-term; online softmax in fragments; P split in-reg;
// O += (Ph+Pl)(Vh+Vl) 3-term (V B-frags via ldmatrix.trans on natural layout).
// ============================================================================
#define AROWB   144                       // 64 dk * 2B + 16 pad
#define ATILE   (64 * AROWB)              // 9216
#define QTILE_A (128 * AROWB)             // 18432
#define AKVST   (4 * ATILE)               // 36864: Kh,Kl,Vh,Vl
#define AMASK   (2 * QTILE_A + 2 * AKVST) // 110592
#define ATT_SMEM (AMASK + SS * 4)         // 114688

__device__ __forceinline__ void load_kv_stage(
    uint32_t st, const __nv_bfloat16* kh, const __nv_bfloat16* kl,
    const __nv_bfloat16* vh, const __nv_bfloat16* vl, int key0, int tid)
{
    #pragma unroll
    for (int j = 0; j < 2; j++) {
        int u = tid + j * 256;
        int row = u >> 3, c = u & 7;
        uint32_t o = row * AROWB + c * 16;
        size_t go = (size_t)(key0 + row) * DKK + c * 8;
        cp_async16(st + o,             kh + go);
        cp_async16(st + ATILE + o,     kl + go);
        cp_async16(st + 2 * ATILE + o, vh + go);
        cp_async16(st + 3 * ATILE + o, vl + go);
    }
}

__global__ void __launch_bounds__(256, 1)
attention_mma(const __nv_bfloat16* __restrict__ qh, const __nv_bfloat16* __restrict__ ql,
              const __nv_bfloat16* __restrict__ kh, const __nv_bfloat16* __restrict__ kl,
              const __nv_bfloat16* __restrict__ vh, const __nv_bfloat16* __restrict__ vl,
              const int* __restrict__ mask,
              __nv_bfloat16* __restrict__ ctxh, __nv_bfloat16* __restrict__ ctxl)
{
    extern __shared__ char sm8[];
    const uint32_t sb = smem_u32(sm8);
    float* sMask = (float*)(sm8 + AMASK);

    const int tid = threadIdx.x, wid = tid >> 5, lane = tid & 31;
    const int bh = blockIdx.y, b = bh >> 4, h = bh & 15;
    const int q0 = blockIdx.x * 128;
    const size_t bhoff = (size_t)bh * (SS * DKK);
    const __nv_bfloat16* khb = kh + bhoff;
    const __nv_bfloat16* klb = kl + bhoff;
    const __nv_bfloat16* vhb = vh + bhoff;
    const __nv_bfloat16* vlb = vl + bhoff;

    // mask -> replace-table (0 = keep, else the replacement value)
    for (int i = tid; i < SS; i += 256)
        sMask[i] = (__ldg(mask + b * SS + i) == 0) ? -1e9f : 0.0f;

    // Q tiles (hi, lo) via cp.async
    {
        const __nv_bfloat16* qhb = qh + bhoff + (size_t)q0 * DKK;
        const __nv_bfloat16* qlb = ql + bhoff + (size_t)q0 * DKK;
        #pragma unroll
        for (int j = 0; j < 4; j++) {
            int u = tid + j * 256;
            int row = u >> 3, c = u & 7;
            uint32_t o = row * AROWB + c * 16;
            size_t go = (size_t)row * DKK + c * 8;
            cp_async16(sb + o, qhb + go);
            cp_async16(sb + QTILE_A + o, qlb + go);
        }
    }
    load_kv_stage(sb + 2 * QTILE_A, khb, klb, vhb, vlb, 0, tid);
    CP_COMMIT();
    load_kv_stage(sb + 2 * QTILE_A + AKVST, khb, klb, vhb, vlb, 64, tid);
    CP_COMMIT();

    asm volatile("cp.async.wait_group 1;" ::: "memory");
    __syncthreads();

    // Q fragments in registers (4 k-steps x hi/lo)
    uint32_t qfh[4][4], qfl[4][4];
    {
        uint32_t base = sb + (wid * 16 + (lane & 15)) * AROWB + (lane >> 4) * 16;
        #pragma unroll
        for (int d = 0; d < 4; d++) {
            ldm_x4(qfh[d], base + d * 32);
            ldm_x4(qfl[d], base + QTILE_A + d * 32);
        }
    }

    float oacc[8][4];
    #pragma unroll
    for (int j = 0; j < 8; j++)
        #pragma unroll
        for (int c = 0; c < 4; c++) oacc[j][c] = 0.0f;
    float mr0 = -1e30f, mr1 = -1e30f, lr0 = 0.0f, lr1 = 0.0f;

    const int q2 = (lane & 3) * 2;

    for (int kt = 0; kt < 16; kt++) {
        asm volatile("cp.async.wait_group 1;" ::: "memory");
        __syncthreads();

        const uint32_t st = sb + 2 * QTILE_A + (kt & 1) * AKVST;

        // ---- S = Q K^T ----
        float sc[8][4];
        #pragma unroll
        for (int j = 0; j < 8; j++)
            #pragma unroll
            for (int c = 0; c < 4; c++) sc[j][c] = 0.0f;

        #pragma unroll
        for (int d = 0; d < 4; d++) {
            const uint32_t kbase = st + (lane & 15) * AROWB + (lane >> 4) * 16 + d * 32;
            #pragma unroll
            for (int kg = 0; kg < 4; kg++) {
                uint32_t kfh[4], kfl[4];
                ldm_x4(kfh, kbase + kg * 16 * AROWB);
                ldm_x4(kfl, kbase + ATILE + kg * 16 * AROWB);
                mma_bf16(sc[2 * kg],     qfh[d], kfh[0], kfh[2]);
                mma_bf16(sc[2 * kg],     qfh[d], kfl[0], kfl[2]);
                mma_bf16(sc[2 * kg],     qfl[d], kfh[0], kfh[2]);
                mma_bf16(sc[2 * kg + 1], qfh[d], kfh[1], kfh[3]);
                mma_bf16(sc[2 * kg + 1], qfh[d], kfl[1], kfl[3]);
                mma_bf16(sc[2 * kg + 1], qfl[d], kfh[1], kfh[3]);
            }
        }

        // ---- mask (replace semantics) ----
        #pragma unroll
        for (int j = 0; j < 8; j++) {
            float f0 = sMask[kt * 64 + j * 8 + q2];
            float f1 = sMask[kt * 64 + j * 8 + q2 + 1];
            if (f0 != 0.0f) { sc[j][0] = f0; sc[j][2] = f0; }
            if (f1 != 0.0f) { sc[j][1] = f1; sc[j][3] = f1; }
        }

        // ---- online softmax (rows g and g+8; quad reduction) ----
        float mt0 = -1e30f, mt1 = -1e30f;
        #pragma unroll
        for (int j = 0; j < 8; j++) {
            mt0 = fmaxf(mt0, fmaxf(sc[j][0], sc[j][1]));
            mt1 = fmaxf(mt1, fmaxf(sc[j][2], sc[j][3]));
        }
        mt0 = fmaxf(mt0, __shfl_xor_sync(0xffffffffu, mt0, 1));
        mt0 = fmaxf(mt0, __shfl_xor_sync(0xffffffffu, mt0, 2));
        mt1 = fmaxf(mt1, __shfl_xor_sync(0xffffffffu, mt1, 1));
        mt1 = fmaxf(mt1, __shfl_xor_sync(0xffffffffu, mt1, 2));

        float mn0 = fmaxf(mr0, mt0), mn1 = fmaxf(mr1, mt1);
        float cr0 = __expf(mr0 - mn0), cr1 = __expf(mr1 - mn1);
        mr0 = mn0; mr1 = mn1;

        float rs0 = 0.0f, rs1 = 0.0f;
        #pragma unroll
        for (int j = 0; j < 8; j++) {
            sc[j][0] = __expf(sc[j][0] - mn0);
            sc[j][1] = __expf(sc[j][1] - mn0);
            sc[j][2] = __expf(sc[j][2] - mn1);
            sc[j][3] = __expf(sc[j][3] - mn1);
            rs0 += sc[j][0] + sc[j][1];
            rs1 += sc[j][2] + sc[j][3];
        }
        rs0 += __shfl_xor_sync(0xffffffffu, rs0, 1);
        rs0 += __shfl_xor_sync(0xffffffffu, rs0, 2);
        rs1 += __shfl_xor_sync(0xffffffffu, rs1, 1);
        rs1 += __shfl_xor_sync(0xffffffffu, rs1, 2);
        lr0 = lr0 * cr0 + rs0;
        lr1 = lr1 * cr1 + rs1;
        #pragma unroll
        for (int j = 0; j < 8; j++) {
            oacc[j][0] *= cr0; oacc[j][1] *= cr0;
            oacc[j][2] *= cr1; oacc[j][3] *= cr1;
        }

        // ---- pack P fragments (C-of-S -> A-of-PV, in registers) ----
        uint32_t pfh[4][4], pfl[4][4];
        #pragma unroll
        for (int m = 0; m < 4; m++) {
            pack_split2(sc[2 * m][0],     sc[2 * m][1],     pfh[m][0], pfl[m][0]);
            pack_split2(sc[2 * m][2],     sc[2 * m][3],     pfh[m][1], pfl[m][1]);
            pack_split2(sc[2 * m + 1][0], sc[2 * m + 1][1], pfh[m][2], pfl[m][2]);
            pack_split2(sc[2 * m + 1][2], sc[2 * m + 1][3], pfh[m][3], pfl[m][3]);
        }

        // ---- O += P V ----
        #pragma unroll
        for (int kp = 0; kp < 2; kp++) {
            const uint32_t vbase = st + 2 * ATILE + (kp * 32 + lane) * AROWB;
            #pragma unroll
            for (int j = 0; j < 8; j++) {
                uint32_t vfh[4], vfl[4];
                ldm_x4_t(vfh, vbase + j * 16);
                ldm_x4_t(vfl, vbase + ATILE + j * 16);
                const int m0_ = 2 * kp, m1_ = 2 * kp + 1;
                mma_bf16(oacc[j], pfh[m0_], vfh[0], vfh[1]);
                mma_bf16(oacc[j], pfh[m0_], vfl[0], vfl[1]);
                mma_bf16(oacc[j], pfl[m0_], vfh[0], vfh[1]);
                mma_bf16(oacc[j], pfh[m1_], vfh[2], vfh[3]);
                mma_bf16(oacc[j], pfh[m1_], vfl[2], vfl[3]);
                mma_bf16(oacc[j], pfl[m1_], vfh[2], vfh[3]);
            }
        }

        __syncthreads();
        if (kt + 2 < 16)
            load_kv_stage(sb + 2 * QTILE_A + (kt & 1) * AKVST,
                          khb, klb, vhb, vlb, (kt + 2) * 64, tid);
        CP_COMMIT();
    }

    // ---- normalize + write ctx hi/lo ----
    const float rinv0 = __fdividef(1.0f, lr0);
    const float rinv1 = __fdividef(1.0f, lr1);
    const int g = lane >> 2;
    const int s0 = q0 + wid * 16 + g;
    size_t base0 = (size_t)(b * SS + s0) * DD + h * DKK;
    size_t base1 = base0 + (size_t)8 * DD;
    #pragma unroll
    for (int j = 0; j < 8; j++) {
        const int col = j * 8 + q2;
        uint32_t hw, lw;
        pack_split2(oacc[j][0] * rinv0, oacc[j][1] * rinv0, hw, lw);
        *(uint32_t*)(ctxh + base0 + col) = hw;
        *(uint32_t*)(ctxl + base0 + col) = lw;
        pack_split2(oacc[j][2] * rinv1, oacc[j][3] * rinv1, hw, lw);
        *(uint32_t*)(ctxh + base1 + col) = hw;
        *(uint32_t*)(ctxl + base1 + col) = lw;
    }
}

// ============================================================================
// Launch
// ============================================================================
extern "C" void kernel_launch(void* const* d_in, const int* in_sizes, int n_in,
                              void* d_out, int out_size)
{
    const float* x      = (const float*)d_in[0];
    const int*   mask   = (const int*)  d_in[1];
    const float* wq     = (const float*)d_in[2];
    const float* bq     = (const float*)d_in[3];
    const float* wk     = (const float*)d_in[4];
    const float* bk     = (const float*)d_in[5];
    const float* wv     = (const float*)d_in[6];
    const float* bv     = (const float*)d_in[7];
    const float* wo     = (const float*)d_in[8];
    const float* bo     = (const float*)d_in[9];
    const float* w1     = (const float*)d_in[10];
    const float* b1     = (const float*)d_in[11];
    const float* w2     = (const float*)d_in[12];
    const float* b2     = (const float*)d_in[13];
    const float* alpha1 = (const float*)d_in[14];
    const float* beta1  = (const float*)d_in[15];
    const float* alpha2 = (const float*)d_in[16];
    const float* beta2  = (const float*)d_in[17];
    float* out = (float*)d_out;

    __nv_bfloat16 *xnh, *xnl, *qh, *ql, *kh, *kl, *vh, *vl;
    __nv_bfloat16 *ctxh, *ctxl, *ffh, *ffl, *wth, *wtl;
    float *x1;
    cudaGetSymbolAddress((void**)&xnh,  g_xnh);
    cudaGetSymbolAddress((void**)&xnl,  g_xnl);
    cudaGetSymbolAddress((void**)&qh,   g_qh);
    cudaGetSymbolAddress((void**)&ql,   g_ql);
    cudaGetSymbolAddress((void**)&kh,   g_kh);
    cudaGetSymbolAddress((void**)&kl,   g_kl);
    cudaGetSymbolAddress((void**)&vh,   g_vh);
    cudaGetSymbolAddress((void**)&vl,   g_vl);
    cudaGetSymbolAddress((void**)&ctxh, g_ctxh);
    cudaGetSymbolAddress((void**)&ctxl, g_ctxl);
    cudaGetSymbolAddress((void**)&x1,   g_x1);
    cudaGetSymbolAddress((void**)&ffh,  g_ffh);
    cudaGetSymbolAddress((void**)&ffl,  g_ffl);
    cudaGetSymbolAddress((void**)&wth,  g_wth);
    cudaGetSymbolAddress((void**)&wtl,  g_wtl);

    cudaFuncSetAttribute(hgemm<1>, cudaFuncAttributeMaxDynamicSharedMemorySize, GEMM_SMEM);
    cudaFuncSetAttribute(hgemm<2>, cudaFuncAttributeMaxDynamicSharedMemorySize, GEMM_SMEM);
    cudaFuncSetAttribute(hgemm<3>, cudaFuncAttributeMaxDynamicSharedMemorySize, GEMM_SMEM);
    cudaFuncSetAttribute(attention_mma, cudaFuncAttributeMaxDynamicSharedMemorySize, ATT_SMEM);

    const size_t MEG = 1024 * 1024;

    // ---- weight transpose + split ----
    wconv_kernel<<<dim3(DD / 32, DD / 32),   dim3(32, 8)>>>(wq, wth + 0 * MEG, wtl + 0 * MEG, DD,  DD);
    wconv_kernel<<<dim3(DD / 32, DD / 32),   dim3(32, 8)>>>(wk, wth + 1 * MEG, wtl + 1 * MEG, DD,  DD);
    wconv_kernel<<<dim3(DD / 32, DD / 32),   dim3(32, 8)>>>(wv, wth + 2 * MEG, wtl + 2 * MEG, DD,  DD);
    wconv_kernel<<<dim3(DD / 32, DD / 32),   dim3(32, 8)>>>(wo, wth + 3 * MEG, wtl + 3 * MEG, DD,  DD);
    wconv_kernel<<<dim3(DFF_ / 32, DD / 32), dim3(32, 8)>>>(w1, wth + 4 * MEG, wtl + 4 * MEG, DD,  DFF_);
    wconv_kernel<<<dim3(DD / 32, DFF_ / 32), dim3(32, 8)>>>(w2, wth + 8 * MEG, wtl + 8 * MEG, DFF_, DD);

    // 1) xn = LN(x) -> hi/lo bf16
    layernorm_bf16<<<ROWS, 256>>>(x, xnh, xnl, alpha1, beta1);

    // 2) q (pre-scaled by 1/8), k, v -> bf16 hi/lo in [B,H,S,DK]
    dim3 gqkv(DD / 128, ROWS / 128);
    hgemm<1><<<gqkv, 256, GEMM_SMEM>>>(xnh, xnl, wth + 0 * MEG, wtl + 0 * MEG, bq, nullptr, nullptr, qh, ql, ROWS, DD, DD, 0.125f);
    hgemm<1><<<gqkv, 256, GEMM_SMEM>>>(xnh, xnl, wth + 1 * MEG, wtl + 1 * MEG, bk, nullptr, nullptr, kh, kl, ROWS, DD, DD, 1.0f);
    hgemm<1><<<gqkv, 256, GEMM_SMEM>>>(xnh, xnl, wth + 2 * MEG, wtl + 2 * MEG, bv, nullptr, nullptr, vh, vl, ROWS, DD, DD, 1.0f);

    // 3) attention -> ctx hi/lo bf16
    attention_mma<<<dim3(SS / 128, BB * HH), 256, ATT_SMEM>>>(qh, ql, kh, kl, vh, vl, mask, ctxh, ctxl);

    // 4) x1 = x + ctx @ wo + bo
    hgemm<2><<<gqkv, 256, GEMM_SMEM>>>(ctxh, ctxl, wth + 3 * MEG, wtl + 3 * MEG, bo, x, x1, nullptr, nullptr, ROWS, DD, DD, 1.0f);

    // 5) xn2 = LN(x1)
    layernorm_bf16<<<ROWS, 256>>>(x1, xnh, xnl, alpha2, beta2);

    // 6) ff = relu(xn2 @ w1 + b1) -> hi/lo bf16
    hgemm<3><<<dim3(DFF_ / 128, ROWS / 128), 256, GEMM_SMEM>>>(xnh, xnl, wth + 4 * MEG, wtl + 4 * MEG, b1, nullptr, nullptr, ffh, ffl, ROWS, DFF_, DD, 1.0f);

    // 7) out = x1 + ff @ w2 + b2
    hgemm<2><<<dim3(DD / 128, ROWS / 128), 256, GEMM_SMEM>>>(ffh, ffl, wth + 8 * MEG, wtl + 8 * MEG, b2, x1, out, nullptr, nullptr, ROWS, DD, DFF_, 1.0f);
}

// round 16
// speedup vs baseline: 3.5064x; 1.3542x over previous
#include <cuda_runtime.h>
#include <cuda_fp16.h>
#include <cuda_bf16.h>
#include <cstdint>
#include <cstddef>

// ============================================================================
// Problem constants: B=4, S=1024, D=1024, H=16, DK=64, DFF=4096
// ============================================================================
#define BB   4
#define SS   1024
#define DD   1024
#define HH   16
#define DKK  64
#define DFF_ 4096
#define ROWS (BB * SS)   // 4096
#define SEGSZ ((size_t)ROWS * DD)

// ---------------------------------------------------------------------------
// Scratch: __device__ globals (no cudaMalloc allowed)
// ---------------------------------------------------------------------------
__device__ __half g_xnh [ROWS * DD];
__device__ __half g_xnl [ROWS * DD];
__device__ __half g_qkvh[3 * ROWS * DD];     // [seg][B,H,S,DK] hi (q,k,v)
__device__ __half g_qkvl[3 * ROWS * DD];     // lo
__device__ __half g_ctxh[ROWS * DD];
__device__ __half g_ctxl[ROWS * DD];
__device__ float  g_x1  [ROWS * DD];
__device__ __half g_ffh [(size_t)ROWS * DFF_];
__device__ __half g_ffl [(size_t)ROWS * DFF_];
// transposed fp16 weights [N,K] K-major: wqkv@0 (3M), wo@3M, w1t@4M, w2t@8M
__device__ __half g_wth [12 * 1024 * 1024];
__device__ float  g_bqkv[3 * DD];

// ---------------------------------------------------------------------------
// PTX helpers (plain-sm_103-legal: cp.async, ldmatrix, mma.sync f16)
// ---------------------------------------------------------------------------
__device__ __forceinline__ uint32_t smem_u32(const void* p) {
    uint32_t a;
    asm("{ .reg .u64 t; cvta.to.shared.u64 t, %1; cvt.u32.u64 %0, t; }"
        : "=r"(a) : "l"(p));
    return a;
}
__device__ __forceinline__ void cp_async16(uint32_t dst, const void* src) {
    asm volatile("cp.async.cg.shared.global [%0], [%1], 16;"
                 :: "r"(dst), "l"(src) : "memory");
}
#define CP_COMMIT() asm volatile("cp.async.commit_group;" ::: "memory")

__device__ __forceinline__ void ldm_x4(uint32_t* r, uint32_t addr) {
    asm volatile("ldmatrix.sync.aligned.m8n8.x4.shared.b16 {%0,%1,%2,%3}, [%4];"
                 : "=r"(r[0]), "=r"(r[1]), "=r"(r[2]), "=r"(r[3]) : "r"(addr));
}
__device__ __forceinline__ void ldm_x4_t(uint32_t* r, uint32_t addr) {
    asm volatile("ldmatrix.sync.aligned.m8n8.x4.trans.shared.b16 {%0,%1,%2,%3}, [%4];"
                 : "=r"(r[0]), "=r"(r[1]), "=r"(r[2]), "=r"(r[3]) : "r"(addr));
}
__device__ __forceinline__ void mma_h(float* c, const uint32_t* a,
                                      uint32_t b0, uint32_t b1) {
    asm volatile(
        "mma.sync.aligned.m16n8k16.row.col.f32.f16.f16.f32 "
        "{%0,%1,%2,%3}, {%4,%5,%6,%7}, {%8,%9}, {%0,%1,%2,%3};"
        : "+f"(c[0]), "+f"(c[1]), "+f"(c[2]), "+f"(c[3])
        : "r"(a[0]), "r"(a[1]), "r"(a[2]), "r"(a[3]), "r"(b0), "r"(b1));
}

// pack two floats into hi/lo fp16x2 words (x -> low half)
__device__ __forceinline__ void pack_split2h(float x, float y,
                                             uint32_t& hw, uint32_t& lw) {
    __half2 h, l;
    h.x = __float2half(x);
    h.y = __float2half(y);
    l.x = __float2half(x - __half2float(h.x));
    l.y = __float2half(y - __half2float(h.y));
    hw = *(uint32_t*)&h;
    lw = *(uint32_t*)&l;
}

// ============================================================================
// LayerNorm -> fp16 hi/lo split output
// ============================================================================
__global__ void __launch_bounds__(256)
layernorm_h(const float* __restrict__ x,
            __half* __restrict__ oh, __half* __restrict__ ol,
            const float* __restrict__ alpha, const float* __restrict__ beta)
{
    __shared__ float red[16];
    const int row = blockIdx.x;
    const int tid = threadIdx.x;
    const float* xr = x + (size_t)row * DD;

    float4 v = *(const float4*)(xr + tid * 4);
    float s = v.x + v.y + v.z + v.w;
    #pragma unroll
    for (int o = 16; o > 0; o >>= 1) s += __shfl_xor_sync(0xffffffffu, s, o);
    if ((tid & 31) == 0) red[tid >> 5] = s;
    __syncthreads();
    float tot = red[0] + red[1] + red[2] + red[3] + red[4] + red[5] + red[6] + red[7];
    float mean = tot * (1.0f / (float)DD);

    float dx0 = v.x - mean, dx1 = v.y - mean, dx2 = v.z - mean, dx3 = v.w - mean;
    float q = dx0 * dx0 + dx1 * dx1 + dx2 * dx2 + dx3 * dx3;
    #pragma unroll
    for (int o = 16; o > 0; o >>= 1) q += __shfl_xor_sync(0xffffffffu, q, o);
    if ((tid & 31) == 0) red[8 + (tid >> 5)] = q;
    __syncthreads();
    float ssq = red[8] + red[9] + red[10] + red[11] + red[12] + red[13] + red[14] + red[15];

    float stdv = sqrtf(ssq * (1.0f / (float)(DD - 1)));
    float a = __ldg(alpha), b = __ldg(beta);
    float r = a / (stdv + 1e-6f);

    float y[4] = {dx0 * r + b, dx1 * r + b, dx2 * r + b, dx3 * r + b};
    uint32_t h01, l01, h23, l23;
    pack_split2h(y[0], y[1], h01, l01);
    pack_split2h(y[2], y[3], h23, l23);
    size_t o0 = (size_t)row * DD + tid * 4;
    *(uint32_t*)(oh + o0)     = h01;
    *(uint32_t*)(oh + o0 + 2) = h23;
    *(uint32_t*)(ol + o0)     = l01;
    *(uint32_t*)(ol + o0 + 2) = l23;
}

// ============================================================================
// Weight transpose to fp16:  W[K,N] fp32 -> Wt [N,K] fp16
// ============================================================================
__global__ void __launch_bounds__(256)
wconv_kernel(const float* __restrict__ W, __half* __restrict__ Th, int K, int N)
{
    __shared__ float t[32][33];
    const int n0 = blockIdx.x * 32, k0 = blockIdx.y * 32;
    const int tx = threadIdx.x, ty = threadIdx.y;
    #pragma unroll
    for (int r = 0; r < 4; r++) {
        int k = k0 + ty + r * 8;
        t[ty + r * 8][tx] = W[(size_t)k * N + n0 + tx];
    }
    __syncthreads();
    #pragma unroll
    for (int r = 0; r < 4; r++) {
        int n = n0 + ty + r * 8;
        int k = k0 + tx;
        Th[(size_t)n * K + k] = __float2half(t[tx][ty + r * 8]);
    }
}

__global__ void bias_concat(const float* __restrict__ bq, const float* __restrict__ bk,
                            const float* __restrict__ bv, float* __restrict__ o)
{
    int i = blockIdx.x * 256 + threadIdx.x;
    if (i < 3 * DD)
        o[i] = (i < DD) ? bq[i] : ((i < 2 * DD) ? bk[i - DD] : bv[i - 2 * DD]);
}

// ============================================================================
// HMMA fp16 2-term GEMM: C[M,N] = (Ah+Al)[M,K] @ Bh[N,K]^T
// CTA 128x128, K-chunk 32, 8 warps (warp tile 32x64), 4-stage cp.async.
// MODE 1: +bias(concat), *0.125 on seg 0, hi/lo scatter [seg][B,H,S,DK]
// MODE 2: +bias +res, fp32
// MODE 3: +bias, ReLU, hi/lo fp16
// ============================================================================
#define BKC     32
#define ROWB    80
#define TILE_B  (128 * ROWB)      // 10240
#define STAGE_B (3 * TILE_B)      // 30720 (Ah, Al, Bh)
#define NSTAGE  4
#define GEMM_SMEM (NSTAGE * STAGE_B + 512 + 128)

__device__ __forceinline__ void load_tile32(uint32_t tb, const __half* src,
                                            int rowBase, int K, int kc, int tid)
{
    #pragma unroll
    for (int j = 0; j < 2; j++) {
        int u = tid + j * 256;
        int row = u >> 2, c = u & 3;
        cp_async16(tb + row * ROWB + c * 16,
                   src + (size_t)(rowBase + row) * K + kc + c * 8);
    }
}

template<int MODE>
__global__ void __launch_bounds__(256, 1)
hgemm(const __half* __restrict__ Ah, const __half* __restrict__ Al,
      const __half* __restrict__ Bh,
      const float* __restrict__ bias, const float* __restrict__ res,
      float* __restrict__ out,
      __half* __restrict__ outh, __half* __restrict__ outl,
      int M, int N, int K)
{
    extern __shared__ char smem[];
    const uint32_t raw = smem_u32(smem);
    const uint32_t sb  = (raw + 127u) & ~127u;
    float* sBias = (float*)(smem + (sb - raw) + NSTAGE * STAGE_B);

    const int tid  = threadIdx.x;
    const int wid  = tid >> 5, lane = tid & 31;
    const int wm   = wid & 3;
    const int wn   = wid >> 2;
    const int m0   = blockIdx.y * 128, n0 = blockIdx.x * 128;
    const int T    = K / BKC;

    if (tid < 128) sBias[tid] = bias[n0 + tid];

    float acc[2][8][4];
    #pragma unroll
    for (int a = 0; a < 2; a++)
        #pragma unroll
        for (int b = 0; b < 8; b++)
            #pragma unroll
            for (int c = 0; c < 4; c++) acc[a][b][c] = 0.0f;

    #pragma unroll
    for (int p = 0; p < NSTAGE - 1; p++) {
        uint32_t st = sb + p * STAGE_B;
        load_tile32(st,              Ah, m0, K, p * BKC, tid);
        load_tile32(st + TILE_B,     Al, m0, K, p * BKC, tid);
        load_tile32(st + 2 * TILE_B, Bh, n0, K, p * BKC, tid);
        CP_COMMIT();
    }

    const uint32_t lrow = lane & 15, lhalf = lane >> 4;

    for (int t = 0; t < T; t++) {
        asm volatile("cp.async.wait_group %0;" :: "n"(NSTAGE - 2) : "memory");
        __syncthreads();

        {
            const int tn = t + NSTAGE - 1;
            if (tn < T) {
                uint32_t st = sb + (tn % NSTAGE) * STAGE_B;
                const int kc = tn * BKC;
                load_tile32(st,              Ah, m0, K, kc, tid);
                load_tile32(st + TILE_B,     Al, m0, K, kc, tid);
                load_tile32(st + 2 * TILE_B, Bh, n0, K, kc, tid);
            }
            CP_COMMIT();
        }

        const uint32_t st = sb + (t % NSTAGE) * STAGE_B;
        #pragma unroll
        for (int ks = 0; ks < 2; ks++) {
            const uint32_t aoff = (wm * 32 + lrow) * ROWB + lhalf * 16 + ks * 32;
            uint32_t ah[2][4], al[2][4];
            ldm_x4(ah[0], st + aoff);
            ldm_x4(ah[1], st + aoff + 16 * ROWB);
            ldm_x4(al[0], st + TILE_B + aoff);
            ldm_x4(al[1], st + TILE_B + aoff + 16 * ROWB);

            const uint32_t boff = (wn * 64 + lrow) * ROWB + lhalf * 16 + ks * 32;
            uint32_t bh[4][4];
            #pragma unroll
            for (int nt = 0; nt < 4; nt++)
                ldm_x4(bh[nt], st + 2 * TILE_B + boff + nt * 16 * ROWB);

            #pragma unroll
            for (int mt = 0; mt < 2; mt++) {
                #pragma unroll
                for (int nt = 0; nt < 4; nt++) {
                    mma_h(acc[mt][2 * nt],     ah[mt], bh[nt][0], bh[nt][2]);
                    mma_h(acc[mt][2 * nt],     al[mt], bh[nt][0], bh[nt][2]);
                    mma_h(acc[mt][2 * nt + 1], ah[mt], bh[nt][1], bh[nt][3]);
                    mma_h(acc[mt][2 * nt + 1], al[mt], bh[nt][1], bh[nt][3]);
                }
            }
        }
    }

    const int g = lane >> 2, qd = lane & 3;
    #pragma unroll
    for (int mt = 0; mt < 2; mt++) {
        #pragma unroll
        for (int jn = 0; jn < 8; jn++) {
            const int gm = m0 + wm * 32 + mt * 16 + g;
            const int gn = n0 + wn * 64 + jn * 8 + qd * 2;
            const float b0 = sBias[gn - n0], b1 = sBias[gn - n0 + 1];
            float v0 = acc[mt][jn][0] + b0;
            float v1 = acc[mt][jn][1] + b1;
            float v2 = acc[mt][jn][2] + b0;
            float v3 = acc[mt][jn][3] + b1;

            if (MODE == 1) {
                const float scl = (gn < DD) ? 0.125f : 1.0f;   // q segment pre-scale
                v0 *= scl; v1 *= scl; v2 *= scl; v3 *= scl;
                const int seg = gn >> 10, np = gn & 1023;
                const int h_ = np >> 6, dk = np & 63;
                const size_t so = (size_t)seg * SEGSZ;
                const int b_  = gm >> 10,       s  = gm & 1023;
                const int b2_ = (gm + 8) >> 10, s2 = (gm + 8) & 1023;
                size_t i0 = so + (((size_t)(b_  * HH + h_) * SS + s ) << 6) + dk;
                size_t i1 = so + (((size_t)(b2_ * HH + h_) * SS + s2) << 6) + dk;
                uint32_t hw, lw;
                pack_split2h(v0, v1, hw, lw);
                *(uint32_t*)(outh + i0) = hw; *(uint32_t*)(outl + i0) = lw;
                pack_split2h(v2, v3, hw, lw);
                *(uint32_t*)(outh + i1) = hw; *(uint32_t*)(outl + i1) = lw;
            } else if (MODE == 2) {
                float2 r0 = *(const float2*)(res + (size_t)gm * N + gn);
                float2 r1 = *(const float2*)(res + (size_t)(gm + 8) * N + gn);
                *(float2*)(out + (size_t)gm * N + gn)       = make_float2(v0 + r0.x, v1 + r0.y);
                *(float2*)(out + (size_t)(gm + 8) * N + gn) = make_float2(v2 + r1.x, v3 + r1.y);
            } else {
                v0 = fmaxf(v0, 0.0f); v1 = fmaxf(v1, 0.0f);
                v2 = fmaxf(v2, 0.0f); v3 = fmaxf(v3, 0.0f);
                uint32_t hw, lw;
                pack_split2h(v0, v1, hw, lw);
                *(uint32_t*)(outh + (size_t)gm * N + gn) = hw;
                *(uint32_t*)(outl + (size_t)gm * N + gn) = lw;
                pack_split2h(v2, v3, hw, lw);
                *(uint32_t*)(outh + (size_t)(gm + 8) * N + gn) = hw;
                *(uint32_t*)(outl + (size_t)(gm + 8) * N + gn) = lw;
            }
        }
    }
}

// ============================================================================
// HMMA flash attention, fp16 2-term. CTA = 128 q-rows x (b,h); 8 warps.
// S = (Qh+Ql) Kh^T; online softmax in fragments; P split in-reg;
// O += (Ph+Pl) Vh (V B-frags via ldmatrix.trans).
// ============================================================================
#define AROWB   144                       // 64 dk * 2B + 16 pad
#define ATILE   (64 * AROWB)              // 9216
#define QTILE_A (128 * AROWB)             // 18432
#define AKVST   (2 * ATILE)               // 18432: Kh, Vh
#define AMASK   (2 * QTILE_A + 2 * AKVST) // 73728
#define ATT_SMEM (AMASK + SS * 4)         // 77824

__device__ __forceinline__ void load_kv_stage(
    uint32_t st, const __half* kh, const __half* vh, int key0, int tid)
{
    #pragma unroll
    for (int j = 0; j < 2; j++) {
        int u = tid + j * 256;
        int row = u >> 3, c = u & 7;
        uint32_t o = row * AROWB + c * 16;
        size_t go = (size_t)(key0 + row) * DKK + c * 8;
        cp_async16(st + o,         kh + go);
        cp_async16(st + ATILE + o, vh + go);
    }
}

__global__ void __launch_bounds__(256, 1)
attention_mma(const __half* __restrict__ qh, const __half* __restrict__ ql,
              const __half* __restrict__ kh, const __half* __restrict__ vh,
              const int* __restrict__ mask,
              __half* __restrict__ ctxh, __half* __restrict__ ctxl)
{
    extern __shared__ char sm8[];
    const uint32_t sb = smem_u32(sm8);
    float* sMask = (float*)(sm8 + AMASK);

    const int tid = threadIdx.x, wid = tid >> 5, lane = tid & 31;
    const int bh = blockIdx.y, b = bh >> 4, h = bh & 15;
    const int q0 = blockIdx.x * 128;
    const size_t bhoff = (size_t)bh * (SS * DKK);
    const __half* khb = kh + bhoff;
    const __half* vhb = vh + bhoff;

    for (int i = tid; i < SS; i += 256)
        sMask[i] = (__ldg(mask + b * SS + i) == 0) ? -1e9f : 0.0f;

    {
        const __half* qhb = qh + bhoff + (size_t)q0 * DKK;
        const __half* qlb = ql + bhoff + (size_t)q0 * DKK;
        #pragma unroll
        for (int j = 0; j < 4; j++) {
            int u = tid + j * 256;
            int row = u >> 3, c = u & 7;
            uint32_t o = row * AROWB + c * 16;
            size_t go = (size_t)row * DKK + c * 8;
            cp_async16(sb + o, qhb + go);
            cp_async16(sb + QTILE_A + o, qlb + go);
        }
    }
    load_kv_stage(sb + 2 * QTILE_A, khb, vhb, 0, tid);
    CP_COMMIT();
    load_kv_stage(sb + 2 * QTILE_A + AKVST, khb, vhb, 64, tid);
    CP_COMMIT();

    asm volatile("cp.async.wait_group 1;" ::: "memory");
    __syncthreads();

    uint32_t qfh[4][4], qfl[4][4];
    {
        uint32_t base = sb + (wid * 16 + (lane & 15)) * AROWB + (lane >> 4) * 16;
        #pragma unroll
        for (int d = 0; d < 4; d++) {
            ldm_x4(qfh[d], base + d * 32);
            ldm_x4(qfl[d], base + QTILE_A + d * 32);
        }
    }

    float oacc[8][4];
    #pragma unroll
    for (int j = 0; j < 8; j++)
        #pragma unroll
        for (int c = 0; c < 4; c++) oacc[j][c] = 0.0f;
    float mr0 = -1e30f, mr1 = -1e30f, lr0 = 0.0f, lr1 = 0.0f;

    const int q2 = (lane & 3) * 2;

    for (int kt = 0; kt < 16; kt++) {
        asm volatile("cp.async.wait_group 1;" ::: "memory");
        __syncthreads();

        const uint32_t st = sb + 2 * QTILE_A + (kt & 1) * AKVST;

        // ---- S = Q K^T (2-term) ----
        float sc[8][4];
        #pragma unroll
        for (int j = 0; j < 8; j++)
            #pragma unroll
            for (int c = 0; c < 4; c++) sc[j][c] = 0.0f;

        #pragma unroll
        for (int d = 0; d < 4; d++) {
            const uint32_t kbase = st + (lane & 15) * AROWB + (lane >> 4) * 16 + d * 32;
            #pragma unroll
            for (int kg = 0; kg < 4; kg++) {
                uint32_t kfh[4];
                ldm_x4(kfh, kbase + kg * 16 * AROWB);
                mma_h(sc[2 * kg],     qfh[d], kfh[0], kfh[2]);
                mma_h(sc[2 * kg],     qfl[d], kfh[0], kfh[2]);
                mma_h(sc[2 * kg + 1], qfh[d], kfh[1], kfh[3]);
                mma_h(sc[2 * kg + 1], qfl[d], kfh[1], kfh[3]);
            }
        }

        // ---- mask (replace semantics) ----
        #pragma unroll
        for (int j = 0; j < 8; j++) {
            float f0 = sMask[kt * 64 + j * 8 + q2];
            float f1 = sMask[kt * 64 + j * 8 + q2 + 1];
            if (f0 != 0.0f) { sc[j][0] = f0; sc[j][2] = f0; }
            if (f1 != 0.0f) { sc[j][1] = f1; sc[j][3] = f1; }
        }

        // ---- online softmax ----
        float mt0 = -1e30f, mt1 = -1e30f;
        #pragma unroll
        for (int j = 0; j < 8; j++) {
            mt0 = fmaxf(mt0, fmaxf(sc[j][0], sc[j][1]));
            mt1 = fmaxf(mt1, fmaxf(sc[j][2], sc[j][3]));
        }
        mt0 = fmaxf(mt0, __shfl_xor_sync(0xffffffffu, mt0, 1));
        mt0 = fmaxf(mt0, __shfl_xor_sync(0xffffffffu, mt0, 2));
        mt1 = fmaxf(mt1, __shfl_xor_sync(0xffffffffu, mt1, 1));
        mt1 = fmaxf(mt1, __shfl_xor_sync(0xffffffffu, mt1, 2));

        float mn0 = fmaxf(mr0, mt0), mn1 = fmaxf(mr1, mt1);
        float cr0 = __expf(mr0 - mn0), cr1 = __expf(mr1 - mn1);
        mr0 = mn0; mr1 = mn1;

        float rs0 = 0.0f, rs1 = 0.0f;
        #pragma unroll
        for (int j = 0; j < 8; j++) {
            sc[j][0] = __expf(sc[j][0] - mn0);
            sc[j][1] = __expf(sc[j][1] - mn0);
            sc[j][2] = __expf(sc[j][2] - mn1);
            sc[j][3] = __expf(sc[j][3] - mn1);
            rs0 += sc[j][0] + sc[j][1];
            rs1 += sc[j][2] + sc[j][3];
        }
        rs0 += __shfl_xor_sync(0xffffffffu, rs0, 1);
        rs0 += __shfl_xor_sync(0xffffffffu, rs0, 2);
        rs1 += __shfl_xor_sync(0xffffffffu, rs1, 1);
        rs1 += __shfl_xor_sync(0xffffffffu, rs1, 2);
        lr0 = lr0 * cr0 + rs0;
        lr1 = lr1 * cr1 + rs1;
        #pragma unroll
        for (int j = 0; j < 8; j++) {
            oacc[j][0] *= cr0; oacc[j][1] *= cr0;
            oacc[j][2] *= cr1; oacc[j][3] *= cr1;
        }

        // ---- pack P fragments (C-of-S -> A-of-PV, in registers) ----
        uint32_t pfh[4][4], pfl[4][4];
        #pragma unroll
        for (int m = 0; m < 4; m++) {
            pack_split2h(sc[2 * m][0],     sc[2 * m][1],     pfh[m][0], pfl[m][0]);
            pack_split2h(sc[2 * m][2],     sc[2 * m][3],     pfh[m][1], pfl[m][1]);
            pack_split2h(sc[2 * m + 1][0], sc[2 * m + 1][1], pfh[m][2], pfl[m][2]);
            pack_split2h(sc[2 * m + 1][2], sc[2 * m + 1][3], pfh[m][3], pfl[m][3]);
        }

        // ---- O += P V (2-term) ----
        #pragma unroll
        for (int kp = 0; kp < 2; kp++) {
            const uint32_t vbase = st + ATILE + (kp * 32 + lane) * AROWB;
            #pragma unroll
            for (int j = 0; j < 8; j++) {
                uint32_t vfh[4];
                ldm_x4_t(vfh, vbase + j * 16);
                const int m0_ = 2 * kp, m1_ = 2 * kp + 1;
                mma_h(oacc[j], pfh[m0_], vfh[0], vfh[1]);
                mma_h(oacc[j], pfl[m0_], vfh[0], vfh[1]);
                mma_h(oacc[j], pfh[m1_], vfh[2], vfh[3]);
                mma_h(oacc[j], pfl[m1_], vfh[2], vfh[3]);
            }
        }

        __syncthreads();
        if (kt + 2 < 16)
            load_kv_stage(sb + 2 * QTILE_A + (kt & 1) * AKVST,
                          khb, vhb, (kt + 2) * 64, tid);
        CP_COMMIT();
    }

    // ---- normalize + write ctx hi/lo ----
    const float rinv0 = __fdividef(1.0f, lr0);
    const float rinv1 = __fdividef(1.0f, lr1);
    const int g = lane >> 2;
    const int s0 = q0 + wid * 16 + g;
    size_t base0 = (size_t)(b * SS + s0) * DD + h * DKK;
    size_t base1 = base0 + (size_t)8 * DD;
    #pragma unroll
    for (int j = 0; j < 8; j++) {
        const int col = j * 8 + q2;
        uint32_t hw, lw;
        pack_split2h(oacc[j][0] * rinv0, oacc[j][1] * rinv0, hw, lw);
        *(uint32_t*)(ctxh + base0 + col) = hw;
        *(uint32_t*)(ctxl + base0 + col) = lw;
        pack_split2h(oacc[j][2] * rinv1, oacc[j][3] * rinv1, hw, lw);
        *(uint32_t*)(ctxh + base1 + col) = hw;
        *(uint32_t*)(ctxl + base1 + col) = lw;
    }
}

// ============================================================================
// Launch
// ============================================================================
extern "C" void kernel_launch(void* const* d_in, const int* in_sizes, int n_in,
                              void* d_out, int out_size)
{
    const float* x      = (const float*)d_in[0];
    const int*   mask   = (const int*)  d_in[1];
    const float* wq     = (const float*)d_in[2];
    const float* bq     = (const float*)d_in[3];
    const float* wk     = (const float*)d_in[4];
    const float* bk     = (const float*)d_in[5];
    const float* wv     = (const float*)d_in[6];
    const float* bv     = (const float*)d_in[7];
    const float* wo     = (const float*)d_in[8];
    const float* bo     = (const float*)d_in[9];
    const float* w1     = (const float*)d_in[10];
    const float* b1     = (const float*)d_in[11];
    const float* w2     = (const float*)d_in[12];
    const float* b2     = (const float*)d_in[13];
    const float* alpha1 = (const float*)d_in[14];
    const float* beta1  = (const float*)d_in[15];
    const float* alpha2 = (const float*)d_in[16];
    const float* beta2  = (const float*)d_in[17];
    float* out = (float*)d_out;

    __half *xnh, *xnl, *qkvh, *qkvl, *ctxh, *ctxl, *ffh, *ffl, *wth;
    float *x1, *bqkv;
    cudaGetSymbolAddress((void**)&xnh,  g_xnh);
    cudaGetSymbolAddress((void**)&xnl,  g_xnl);
    cudaGetSymbolAddress((void**)&qkvh, g_qkvh);
    cudaGetSymbolAddress((void**)&qkvl, g_qkvl);
    cudaGetSymbolAddress((void**)&ctxh, g_ctxh);
    cudaGetSymbolAddress((void**)&ctxl, g_ctxl);
    cudaGetSymbolAddress((void**)&x1,   g_x1);
    cudaGetSymbolAddress((void**)&ffh,  g_ffh);
    cudaGetSymbolAddress((void**)&ffl,  g_ffl);
    cudaGetSymbolAddress((void**)&wth,  g_wth);
    cudaGetSymbolAddress((void**)&bqkv, g_bqkv);

    cudaFuncSetAttribute(hgemm<1>, cudaFuncAttributeMaxDynamicSharedMemorySize, GEMM_SMEM);
    cudaFuncSetAttribute(hgemm<2>, cudaFuncAttributeMaxDynamicSharedMemorySize, GEMM_SMEM);
    cudaFuncSetAttribute(hgemm<3>, cudaFuncAttributeMaxDynamicSharedMemorySize, GEMM_SMEM);
    cudaFuncSetAttribute(attention_mma, cudaFuncAttributeMaxDynamicSharedMemorySize, ATT_SMEM);

    const size_t MEG = 1024 * 1024;

    // ---- weight transpose to fp16 [N,K]; wq/wk/wv land contiguous = [3072,1024] ----
    wconv_kernel<<<dim3(DD / 32, DD / 32),   dim3(32, 8)>>>(wq, wth + 0 * MEG, DD,  DD);
    wconv_kernel<<<dim3(DD / 32, DD / 32),   dim3(32, 8)>>>(wk, wth + 1 * MEG, DD,  DD);
    wconv_kernel<<<dim3(DD / 32, DD / 32),   dim3(32, 8)>>>(wv, wth + 2 * MEG, DD,  DD);
    wconv_kernel<<<dim3(DD / 32, DD / 32),   dim3(32, 8)>>>(wo, wth + 3 * MEG, DD,  DD);
    wconv_kernel<<<dim3(DFF_ / 32, DD / 32), dim3(32, 8)>>>(w1, wth + 4 * MEG, DD,  DFF_);
    wconv_kernel<<<dim3(DD / 32, DFF_ / 32), dim3(32, 8)>>>(w2, wth + 8 * MEG, DFF_, DD);
    bias_concat<<<12, 256>>>(bq, bk, bv, bqkv);

    // 1) xn = LN(x) -> hi/lo fp16
    layernorm_h<<<ROWS, 256>>>(x, xnh, xnl, alpha1, beta1);

    // 2) fused QKV GEMM -> hi/lo fp16 scattered [seg][B,H,S,DK] (q pre-scaled)
    hgemm<1><<<dim3(3 * DD / 128, ROWS / 128), 256, GEMM_SMEM>>>(
        xnh, xnl, wth, bqkv, nullptr, nullptr, qkvh, qkvl, ROWS, 3 * DD, DD);

    // 3) attention -> ctx hi/lo fp16
    attention_mma<<<dim3(SS / 128, BB * HH), 256, ATT_SMEM>>>(
        qkvh, qkvl, qkvh + SEGSZ, qkvh + 2 * SEGSZ, mask, ctxh, ctxl);

    // 4) x1 = x + ctx @ wo + bo
    hgemm<2><<<dim3(DD / 128, ROWS / 128), 256, GEMM_SMEM>>>(
        ctxh, ctxl, wth + 3 * MEG, bo, x, x1, nullptr, nullptr, ROWS, DD, DD);

    // 5) xn2 = LN(x1)
    layernorm_h<<<ROWS, 256>>>(x1, xnh, xnl, alpha2, beta2);

    // 6) ff = relu(xn2 @ w1 + b1) -> hi/lo fp16
    hgemm<3><<<dim3(DFF_ / 128, ROWS / 128), 256, GEMM_SMEM>>>(
        xnh, xnl, wth + 4 * MEG, b1, nullptr, nullptr, ffh, ffl, ROWS, DFF_, DD);

    // 7) out = x1 + ff @ w2 + b2
    hgemm<2><<<dim3(DD / 128, ROWS / 128), 256, GEMM_SMEM>>>(
        ffh, ffl, wth + 8 * MEG, b2, x1, out, nullptr, nullptr, ROWS, DD, DFF_);
}

// round 17
// speedup vs baseline: 6.0255x; 1.7184x over previous
#include <cuda_runtime.h>
#include <cuda_fp16.h>
#include <cstdint>
#include <cstddef>

// ============================================================================
// Problem constants: B=4, S=1024, D=1024, H=16, DK=64, DFF=4096
// ============================================================================
#define BB   4
#define SS   1024
#define DD   1024
#define HH   16
#define DKK  64
#define DFF_ 4096
#define ROWS (BB * SS)   // 4096
#define SEGSZ ((size_t)ROWS * DD)

// ---------------------------------------------------------------------------
// Scratch: __device__ globals (no cudaMalloc allowed)
// ---------------------------------------------------------------------------
__device__ __half g_xn  [ROWS * DD];
__device__ __half g_qkv [3 * ROWS * DD];     // [seg][B,H,S,DK] (q,k,v)
__device__ __half g_ctx [ROWS * DD];
__device__ float  g_x1  [ROWS * DD];
__device__ __half g_ff  [(size_t)ROWS * DFF_];
// transposed fp16 weights [N,K] K-major: wqkv@0 (3M), wo@3M, w1t@4M, w2t@8M
__device__ __half g_wth [12 * 1024 * 1024];
__device__ float  g_bqkv[3 * DD];

// ---------------------------------------------------------------------------
// PTX helpers (plain-sm_103-legal: cp.async, ldmatrix, mma.sync f16)
// ---------------------------------------------------------------------------
__device__ __forceinline__ uint32_t smem_u32(const void* p) {
    uint32_t a;
    asm("{ .reg .u64 t; cvta.to.shared.u64 t, %1; cvt.u32.u64 %0, t; }"
        : "=r"(a) : "l"(p));
    return a;
}
__device__ __forceinline__ void cp_async16(uint32_t dst, const void* src) {
    asm volatile("cp.async.cg.shared.global [%0], [%1], 16;"
                 :: "r"(dst), "l"(src) : "memory");
}
#define CP_COMMIT() asm volatile("cp.async.commit_group;" ::: "memory")

__device__ __forceinline__ void ldm_x4(uint32_t* r, uint32_t addr) {
    asm volatile("ldmatrix.sync.aligned.m8n8.x4.shared.b16 {%0,%1,%2,%3}, [%4];"
                 : "=r"(r[0]), "=r"(r[1]), "=r"(r[2]), "=r"(r[3]) : "r"(addr));
}
__device__ __forceinline__ void ldm_x4_t(uint32_t* r, uint32_t addr) {
    asm volatile("ldmatrix.sync.aligned.m8n8.x4.trans.shared.b16 {%0,%1,%2,%3}, [%4];"
                 : "=r"(r[0]), "=r"(r[1]), "=r"(r[2]), "=r"(r[3]) : "r"(addr));
}
__device__ __forceinline__ void mma_h(float* c, const uint32_t* a,
                                      uint32_t b0, uint32_t b1) {
    asm volatile(
        "mma.sync.aligned.m16n8k16.row.col.f32.f16.f16.f32 "
        "{%0,%1,%2,%3}, {%4,%5,%6,%7}, {%8,%9}, {%0,%1,%2,%3};"
        : "+f"(c[0]), "+f"(c[1]), "+f"(c[2]), "+f"(c[3])
        : "r"(a[0]), "r"(a[1]), "r"(a[2]), "r"(a[3]), "r"(b0), "r"(b1));
}

// pack two floats into one fp16x2 word (x -> low half)
__device__ __forceinline__ uint32_t pack2h(float x, float y) {
    __half2 h;
    h.x = __float2half(x);
    h.y = __float2half(y);
    return *(uint32_t*)&h;
}

// ============================================================================
// LayerNorm -> fp16 output
// ============================================================================
__global__ void __launch_bounds__(256)
layernorm_h(const float* __restrict__ x, __half* __restrict__ oh,
            const float* __restrict__ alpha, const float* __restrict__ beta)
{
    __shared__ float red[16];
    const int row = blockIdx.x;
    const int tid = threadIdx.x;
    const float* xr = x + (size_t)row * DD;

    float4 v = *(const float4*)(xr + tid * 4);
    float s = v.x + v.y + v.z + v.w;
    #pragma unroll
    for (int o = 16; o > 0; o >>= 1) s += __shfl_xor_sync(0xffffffffu, s, o);
    if ((tid & 31) == 0) red[tid >> 5] = s;
    __syncthreads();
    float tot = red[0] + red[1] + red[2] + red[3] + red[4] + red[5] + red[6] + red[7];
    float mean = tot * (1.0f / (float)DD);

    float dx0 = v.x - mean, dx1 = v.y - mean, dx2 = v.z - mean, dx3 = v.w - mean;
    float q = dx0 * dx0 + dx1 * dx1 + dx2 * dx2 + dx3 * dx3;
    #pragma unroll
    for (int o = 16; o > 0; o >>= 1) q += __shfl_xor_sync(0xffffffffu, q, o);
    if ((tid & 31) == 0) red[8 + (tid >> 5)] = q;
    __syncthreads();
    float ssq = red[8] + red[9] + red[10] + red[11] + red[12] + red[13] + red[14] + red[15];

    float stdv = sqrtf(ssq * (1.0f / (float)(DD - 1)));
    float a = __ldg(alpha), b = __ldg(beta);
    float r = a / (stdv + 1e-6f);

    size_t o0 = (size_t)row * DD + tid * 4;
    *(uint32_t*)(oh + o0)     = pack2h(dx0 * r + b, dx1 * r + b);
    *(uint32_t*)(oh + o0 + 2) = pack2h(dx2 * r + b, dx3 * r + b);
}

// ============================================================================
// Weight transpose to fp16:  W[K,N] fp32 -> Wt [N,K] fp16
// ============================================================================
__global__ void __launch_bounds__(256)
wconv_kernel(const float* __restrict__ W, __half* __restrict__ Th, int K, int N)
{
    __shared__ float t[32][33];
    const int n0 = blockIdx.x * 32, k0 = blockIdx.y * 32;
    const int tx = threadIdx.x, ty = threadIdx.y;
    #pragma unroll
    for (int r = 0; r < 4; r++) {
        int k = k0 + ty + r * 8;
        t[ty + r * 8][tx] = W[(size_t)k * N + n0 + tx];
    }
    __syncthreads();
    #pragma unroll
    for (int r = 0; r < 4; r++) {
        int n = n0 + ty + r * 8;
        int k = k0 + tx;
        Th[(size_t)n * K + k] = __float2half(t[tx][ty + r * 8]);
    }
}

__global__ void bias_concat(const float* __restrict__ bq, const float* __restrict__ bk,
                            const float* __restrict__ bv, float* __restrict__ o)
{
    int i = blockIdx.x * 256 + threadIdx.x;
    if (i < 3 * DD)
        o[i] = (i < DD) ? bq[i] : ((i < 2 * DD) ? bk[i - DD] : bv[i - 2 * DD]);
}

// ============================================================================
// HMMA fp16 GEMM: C[M,N] = A[M,K] @ B[N,K]^T (+bias ...)
// CTA 128x128, K-chunk 32, 8 warps (warp tile 32x64), 5-stage cp.async.
// MODE 1: +bias(concat), *0.125 on seg 0, fp16 scatter [seg][B,H,S,DK]
// MODE 2: +bias +res, fp32
// MODE 3: +bias, ReLU, fp16
// ============================================================================
#define BKC     32
#define ROWB    80
#define TILE_B  (128 * ROWB)      // 10240
#define STAGE_B (2 * TILE_B)      // 20480 (A, B)
#define NSTAGE  5
#define GEMM_SMEM (NSTAGE * STAGE_B + 512 + 128)

__device__ __forceinline__ void load_tile32(uint32_t tb, const __half* src,
                                            int rowBase, int K, int kc, int tid)
{
    #pragma unroll
    for (int j = 0; j < 2; j++) {
        int u = tid + j * 256;
        int row = u >> 2, c = u & 3;
        cp_async16(tb + row * ROWB + c * 16,
                   src + (size_t)(rowBase + row) * K + kc + c * 8);
    }
}

template<int MODE>
__global__ void __launch_bounds__(256, 1)
hgemm(const __half* __restrict__ Ah, const __half* __restrict__ Bh,
      const float* __restrict__ bias, const float* __restrict__ res,
      float* __restrict__ out, __half* __restrict__ outh,
      int M, int N, int K)
{
    extern __shared__ char smem[];
    const uint32_t raw = smem_u32(smem);
    const uint32_t sb  = (raw + 127u) & ~127u;
    float* sBias = (float*)(smem + (sb - raw) + NSTAGE * STAGE_B);

    const int tid  = threadIdx.x;
    const int wid  = tid >> 5, lane = tid & 31;
    const int wm   = wid & 3;
    const int wn   = wid >> 2;
    const int m0   = blockIdx.y * 128, n0 = blockIdx.x * 128;
    const int T    = K / BKC;

    if (tid < 128) sBias[tid] = bias[n0 + tid];

    float acc[2][8][4];
    #pragma unroll
    for (int a = 0; a < 2; a++)
        #pragma unroll
        for (int b = 0; b < 8; b++)
            #pragma unroll
            for (int c = 0; c < 4; c++) acc[a][b][c] = 0.0f;

    #pragma unroll
    for (int p = 0; p < NSTAGE - 1; p++) {
        uint32_t st = sb + p * STAGE_B;
        load_tile32(st,          Ah, m0, K, p * BKC, tid);
        load_tile32(st + TILE_B, Bh, n0, K, p * BKC, tid);
        CP_COMMIT();
    }

    const uint32_t lrow = lane & 15, lhalf = lane >> 4;

    for (int t = 0; t < T; t++) {
        asm volatile("cp.async.wait_group %0;" :: "n"(NSTAGE - 2) : "memory");
        __syncthreads();

        {
            const int tn = t + NSTAGE - 1;
            if (tn < T) {
                uint32_t st = sb + (tn % NSTAGE) * STAGE_B;
                const int kc = tn * BKC;
                load_tile32(st,          Ah, m0, K, kc, tid);
                load_tile32(st + TILE_B, Bh, n0, K, kc, tid);
            }
            CP_COMMIT();
        }

        const uint32_t st = sb + (t % NSTAGE) * STAGE_B;
        #pragma unroll
        for (int ks = 0; ks < 2; ks++) {
            const uint32_t aoff = (wm * 32 + lrow) * ROWB + lhalf * 16 + ks * 32;
            uint32_t ah[2][4];
            ldm_x4(ah[0], st + aoff);
            ldm_x4(ah[1], st + aoff + 16 * ROWB);

            const uint32_t boff = (wn * 64 + lrow) * ROWB + lhalf * 16 + ks * 32;
            uint32_t bh[4][4];
            #pragma unroll
            for (int nt = 0; nt < 4; nt++)
                ldm_x4(bh[nt], st + TILE_B + boff + nt * 16 * ROWB);

            #pragma unroll
            for (int mt = 0; mt < 2; mt++) {
                #pragma unroll
                for (int nt = 0; nt < 4; nt++) {
                    mma_h(acc[mt][2 * nt],     ah[mt], bh[nt][0], bh[nt][2]);
                    mma_h(acc[mt][2 * nt + 1], ah[mt], bh[nt][1], bh[nt][3]);
                }
            }
        }
    }

    const int g = lane >> 2, qd = lane & 3;
    #pragma unroll
    for (int mt = 0; mt < 2; mt++) {
        #pragma unroll
        for (int jn = 0; jn < 8; jn++) {
            const int gm = m0 + wm * 32 + mt * 16 + g;
            const int gn = n0 + wn * 64 + jn * 8 + qd * 2;
            const float b0 = sBias[gn - n0], b1 = sBias[gn - n0 + 1];
            float v0 = acc[mt][jn][0] + b0;
            float v1 = acc[mt][jn][1] + b1;
            float v2 = acc[mt][jn][2] + b0;
            float v3 = acc[mt][jn][3] + b1;

            if (MODE == 1) {
                const float scl = (gn < DD) ? 0.125f : 1.0f;   // q segment pre-scale
                v0 *= scl; v1 *= scl; v2 *= scl; v3 *= scl;
                const int seg = gn >> 10, np = gn & 1023;
                const int h_ = np >> 6, dk = np & 63;
                const size_t so = (size_t)seg * SEGSZ;
                const int b_  = gm >> 10,       s  = gm & 1023;
                const int b2_ = (gm + 8) >> 10, s2 = (gm + 8) & 1023;
                size_t i0 = so + (((size_t)(b_  * HH + h_) * SS + s ) << 6) + dk;
                size_t i1 = so + (((size_t)(b2_ * HH + h_) * SS + s2) << 6) + dk;
                *(uint32_t*)(outh + i0) = pack2h(v0, v1);
                *(uint32_t*)(outh + i1) = pack2h(v2, v3);
            } else if (MODE == 2) {
                float2 r0 = *(const float2*)(res + (size_t)gm * N + gn);
                float2 r1 = *(const float2*)(res + (size_t)(gm + 8) * N + gn);
                *(float2*)(out + (size_t)gm * N + gn)       = make_float2(v0 + r0.x, v1 + r0.y);
                *(float2*)(out + (size_t)(gm + 8) * N + gn) = make_float2(v2 + r1.x, v3 + r1.y);
            } else {
                v0 = fmaxf(v0, 0.0f); v1 = fmaxf(v1, 0.0f);
                v2 = fmaxf(v2, 0.0f); v3 = fmaxf(v3, 0.0f);
                *(uint32_t*)(outh + (size_t)gm * N + gn)       = pack2h(v0, v1);
                *(uint32_t*)(outh + (size_t)(gm + 8) * N + gn) = pack2h(v2, v3);
            }
        }
    }
}

// ============================================================================
// HMMA flash attention, fp16. CTA = 128 q-rows x (b,h); 8 warps, warp = m16.
// S = Q K^T; online softmax in fragments; P packed in-reg (C-of-S -> A-of-PV);
// O += P V (V B-frags via ldmatrix.trans on the natural [key][dk] layout).
// ============================================================================
#define AROWB   144                       // 64 dk * 2B + 16 pad
#define ATILE   (64 * AROWB)              // 9216
#define QTILE_A (128 * AROWB)             // 18432
#define AKVST   (2 * ATILE)               // 18432: K, V
#define AMASK   (QTILE_A + 2 * AKVST)     // 55296
#define ATT_SMEM (AMASK + SS * 4)         // 59392

__device__ __forceinline__ void load_kv_stage(
    uint32_t st, const __half* kh, const __half* vh, int key0, int tid)
{
    #pragma unroll
    for (int j = 0; j < 2; j++) {
        int u = tid + j * 256;
        int row = u >> 3, c = u & 7;
        uint32_t o = row * AROWB + c * 16;
        size_t go = (size_t)(key0 + row) * DKK + c * 8;
        cp_async16(st + o,         kh + go);
        cp_async16(st + ATILE + o, vh + go);
    }
}

__global__ void __launch_bounds__(256, 1)
attention_mma(const __half* __restrict__ qh,
              const __half* __restrict__ kh, const __half* __restrict__ vh,
              const int* __restrict__ mask, __half* __restrict__ ctx)
{
    extern __shared__ char sm8[];
    const uint32_t sb = smem_u32(sm8);
    float* sMask = (float*)(sm8 + AMASK);

    const int tid = threadIdx.x, wid = tid >> 5, lane = tid & 31;
    const int bh = blockIdx.y, b = bh >> 4, h = bh & 15;
    const int q0 = blockIdx.x * 128;
    const size_t bhoff = (size_t)bh * (SS * DKK);
    const __half* khb = kh + bhoff;
    const __half* vhb = vh + bhoff;

    for (int i = tid; i < SS; i += 256)
        sMask[i] = (__ldg(mask + b * SS + i) == 0) ? -1e9f : 0.0f;

    {
        const __half* qhb = qh + bhoff + (size_t)q0 * DKK;
        #pragma unroll
        for (int j = 0; j < 4; j++) {
            int u = tid + j * 256;
            int row = u >> 3, c = u & 7;
            cp_async16(sb + row * AROWB + c * 16, qhb + (size_t)row * DKK + c * 8);
        }
    }
    load_kv_stage(sb + QTILE_A, khb, vhb, 0, tid);
    CP_COMMIT();
    load_kv_stage(sb + QTILE_A + AKVST, khb, vhb, 64, tid);
    CP_COMMIT();

    asm volatile("cp.async.wait_group 1;" ::: "memory");
    __syncthreads();

    uint32_t qf[4][4];
    {
        uint32_t base = sb + (wid * 16 + (lane & 15)) * AROWB + (lane >> 4) * 16;
        #pragma unroll
        for (int d = 0; d < 4; d++) ldm_x4(qf[d], base + d * 32);
    }

    float oacc[8][4];
    #pragma unroll
    for (int j = 0; j < 8; j++)
        #pragma unroll
        for (int c = 0; c < 4; c++) oacc[j][c] = 0.0f;
    float mr0 = -1e30f, mr1 = -1e30f, lr0 = 0.0f, lr1 = 0.0f;

    const int q2 = (lane & 3) * 2;

    for (int kt = 0; kt < 16; kt++) {
        asm volatile("cp.async.wait_group 1;" ::: "memory");
        __syncthreads();

        const uint32_t st = sb + QTILE_A + (kt & 1) * AKVST;

        // ---- S = Q K^T ----
        float sc[8][4];
        #pragma unroll
        for (int j = 0; j < 8; j++)
            #pragma unroll
            for (int c = 0; c < 4; c++) sc[j][c] = 0.0f;

        #pragma unroll
        for (int d = 0; d < 4; d++) {
            const uint32_t kbase = st + (lane & 15) * AROWB + (lane >> 4) * 16 + d * 32;
            #pragma unroll
            for (int kg = 0; kg < 4; kg++) {
                uint32_t kf[4];
                ldm_x4(kf, kbase + kg * 16 * AROWB);
                mma_h(sc[2 * kg],     qf[d], kf[0], kf[2]);
                mma_h(sc[2 * kg + 1], qf[d], kf[1], kf[3]);
            }
        }

        // ---- mask (replace semantics) ----
        #pragma unroll
        for (int j = 0; j < 8; j++) {
            float f0 = sMask[kt * 64 + j * 8 + q2];
            float f1 = sMask[kt * 64 + j * 8 + q2 + 1];
            if (f0 != 0.0f) { sc[j][0] = f0; sc[j][2] = f0; }
            if (f1 != 0.0f) { sc[j][1] = f1; sc[j][3] = f1; }
        }

        // ---- online softmax (rows g and g+8; quad reduction) ----
        float mt0 = -1e30f, mt1 = -1e30f;
        #pragma unroll
        for (int j = 0; j < 8; j++) {
            mt0 = fmaxf(mt0, fmaxf(sc[j][0], sc[j][1]));
            mt1 = fmaxf(mt1, fmaxf(sc[j][2], sc[j][3]));
        }
        mt0 = fmaxf(mt0, __shfl_xor_sync(0xffffffffu, mt0, 1));
        mt0 = fmaxf(mt0, __shfl_xor_sync(0xffffffffu, mt0, 2));
        mt1 = fmaxf(mt1, __shfl_xor_sync(0xffffffffu, mt1, 1));
        mt1 = fmaxf(mt1, __shfl_xor_sync(0xffffffffu, mt1, 2));

        float mn0 = fmaxf(mr0, mt0), mn1 = fmaxf(mr1, mt1);
        float cr0 = __expf(mr0 - mn0), cr1 = __expf(mr1 - mn1);
        mr0 = mn0; mr1 = mn1;

        float rs0 = 0.0f, rs1 = 0.0f;
        #pragma unroll
        for (int j = 0; j < 8; j++) {
            sc[j][0] = __expf(sc[j][0] - mn0);
            sc[j][1] = __expf(sc[j][1] - mn0);
            sc[j][2] = __expf(sc[j][2] - mn1);
            sc[j][3] = __expf(sc[j][3] - mn1);
            rs0 += sc[j][0] + sc[j][1];
            rs1 += sc[j][2] + sc[j][3];
        }
        rs0 += __shfl_xor_sync(0xffffffffu, rs0, 1);
        rs0 += __shfl_xor_sync(0xffffffffu, rs0, 2);
        rs1 += __shfl_xor_sync(0xffffffffu, rs1, 1);
        rs1 += __shfl_xor_sync(0xffffffffu, rs1, 2);
        lr0 = lr0 * cr0 + rs0;
        lr1 = lr1 * cr1 + rs1;
        #pragma unroll
        for (int j = 0; j < 8; j++) {
            oacc[j][0] *= cr0; oacc[j][1] *= cr0;
            oacc[j][2] *= cr1; oacc[j][3] *= cr1;
        }

        // ---- pack P fragments (C-of-S -> A-of-PV, in registers) ----
        uint32_t pf[4][4];
        #pragma unroll
        for (int m = 0; m < 4; m++) {
            pf[m][0] = pack2h(sc[2 * m][0],     sc[2 * m][1]);
            pf[m][1] = pack2h(sc[2 * m][2],     sc[2 * m][3]);
            pf[m][2] = pack2h(sc[2 * m + 1][0], sc[2 * m + 1][1]);
            pf[m][3] = pack2h(sc[2 * m + 1][2], sc[2 * m + 1][3]);
        }

        // ---- O += P V ----
        #pragma unroll
        for (int kp = 0; kp < 2; kp++) {
            const uint32_t vbase = st + ATILE + (kp * 32 + lane) * AROWB;
            #pragma unroll
            for (int j = 0; j < 8; j++) {
                uint32_t vf[4];
                ldm_x4_t(vf, vbase + j * 16);
                mma_h(oacc[j], pf[2 * kp],     vf[0], vf[1]);
                mma_h(oacc[j], pf[2 * kp + 1], vf[2], vf[3]);
            }
        }

        __syncthreads();
        if (kt + 2 < 16)
            load_kv_stage(sb + QTILE_A + (kt & 1) * AKVST,
                          khb, vhb, (kt + 2) * 64, tid);
        CP_COMMIT();
    }

    // ---- normalize + write ctx fp16 ----
    const float rinv0 = __fdividef(1.0f, lr0);
    const float rinv1 = __fdividef(1.0f, lr1);
    const int g = lane >> 2;
    const int s0 = q0 + wid * 16 + g;
    size_t base0 = (size_t)(b * SS + s0) * DD + h * DKK;
    size_t base1 = base0 + (size_t)8 * DD;
    #pragma unroll
    for (int j = 0; j < 8; j++) {
        const int col = j * 8 + q2;
        *(uint32_t*)(ctx + base0 + col) = pack2h(oacc[j][0] * rinv0, oacc[j][1] * rinv0);
        *(uint32_t*)(ctx + base1 + col) = pack2h(oacc[j][2] * rinv1, oacc[j][3] * rinv1);
    }
}

// ============================================================================
// Launch
// ============================================================================
extern "C" void kernel_launch(void* const* d_in, const int* in_sizes, int n_in,
                              void* d_out, int out_size)
{
    const float* x      = (const float*)d_in[0];
    const int*   mask   = (const int*)  d_in[1];
    const float* wq     = (const float*)d_in[2];
    const float* bq     = (const float*)d_in[3];
    const float* wk     = (const float*)d_in[4];
    const float* bk     = (const float*)d_in[5];
    const float* wv     = (const float*)d_in[6];
    const float* bv     = (const float*)d_in[7];
    const float* wo     = (const float*)d_in[8];
    const float* bo     = (const float*)d_in[9];
    const float* w1     = (const float*)d_in[10];
    const float* b1     = (const float*)d_in[11];
    const float* w2     = (const float*)d_in[12];
    const float* b2     = (const float*)d_in[13];
    const float* alpha1 = (const float*)d_in[14];
    const float* beta1  = (const float*)d_in[15];
    const float* alpha2 = (const float*)d_in[16];
    const float* beta2  = (const float*)d_in[17];
    float* out = (float*)d_out;

    __half *xn, *qkv, *ctx, *ff, *wth;
    float *x1, *bqkv;
    cudaGetSymbolAddress((void**)&xn,   g_xn);
    cudaGetSymbolAddress((void**)&qkv,  g_qkv);
    cudaGetSymbolAddress((void**)&ctx,  g_ctx);
    cudaGetSymbolAddress((void**)&x1,   g_x1);
    cudaGetSymbolAddress((void**)&ff,   g_ff);
    cudaGetSymbolAddress((void**)&wth,  g_wth);
    cudaGetSymbolAddress((void**)&bqkv, g_bqkv);

    cudaFuncSetAttribute(hgemm<1>, cudaFuncAttributeMaxDynamicSharedMemorySize, GEMM_SMEM);
    cudaFuncSetAttribute(hgemm<2>, cudaFuncAttributeMaxDynamicSharedMemorySize, GEMM_SMEM);
    cudaFuncSetAttribute(hgemm<3>, cudaFuncAttributeMaxDynamicSharedMemorySize, GEMM_SMEM);
    cudaFuncSetAttribute(attention_mma, cudaFuncAttributeMaxDynamicSharedMemorySize, ATT_SMEM);

    const size_t MEG = 1024 * 1024;

    // ---- weight transpose to fp16 [N,K]; wq/wk/wv contiguous = [3072,1024] ----
    wconv_kernel<<<dim3(DD / 32, DD / 32),   dim3(32, 8)>>>(wq, wth + 0 * MEG, DD,  DD);
    wconv_kernel<<<dim3(DD / 32, DD / 32),   dim3(32, 8)>>>(wk, wth + 1 * MEG, DD,  DD);
    wconv_kernel<<<dim3(DD / 32, DD / 32),   dim3(32, 8)>>>(wv, wth + 2 * MEG, DD,  DD);
    wconv_kernel<<<dim3(DD / 32, DD / 32),   dim3(32, 8)>>>(wo, wth + 3 * MEG, DD,  DD);
    wconv_kernel<<<dim3(DFF_ / 32, DD / 32), dim3(32, 8)>>>(w1, wth + 4 * MEG, DD,  DFF_);
    wconv_kernel<<<dim3(DD / 32, DFF_ / 32), dim3(32, 8)>>>(w2, wth + 8 * MEG, DFF_, DD);
    bias_concat<<<12, 256>>>(bq, bk, bv, bqkv);

    // 1) xn = LN(x) -> fp16
    layernorm_h<<<ROWS, 256>>>(x, xn, alpha1, beta1);

    // 2) fused QKV GEMM -> fp16 scattered [seg][B,H,S,DK] (q pre-scaled by 1/8)
    hgemm<1><<<dim3(3 * DD / 128, ROWS / 128), 256, GEMM_SMEM>>>(
        xn, wth, bqkv, nullptr, nullptr, qkv, ROWS, 3 * DD, DD);

    // 3) attention -> ctx fp16
    attention_mma<<<dim3(SS / 128, BB * HH), 256, ATT_SMEM>>>(
        qkv, qkv + SEGSZ, qkv + 2 * SEGSZ, mask, ctx);

    // 4) x1 = x + ctx @ wo + bo
    hgemm<2><<<dim3(DD / 128, ROWS / 128), 256, GEMM_SMEM>>>(
        ctx, wth + 3 * MEG, bo, x, x1, nullptr, ROWS, DD, DD);

    // 5) xn2 = LN(x1)
    layernorm_h<<<ROWS, 256>>>(x1, xn, alpha2, beta2);

    // 6) ff = relu(xn2 @ w1 + b1) -> fp16
    hgemm<3><<<dim3(DFF_ / 128, ROWS / 128), 256, GEMM_SMEM>>>(
        xn, wth + 4 * MEG, b1, nullptr, nullptr, ff, ROWS, DFF_, DD);

    // 7) out = x1 + ff @ w2 + b2
    hgemm<2><<<dim3(DD / 128, ROWS / 128), 256, GEMM_SMEM>>>(
        ff, wth + 8 * MEG, b2, x1, out, nullptr, ROWS, DD, DFF_);
}